// round 10
// baseline (speedup 1.0000x reference)
#include <cuda_runtime.h>
#include <cstdint>
#include <cstddef>

// ---------------- problem constants ----------------
static constexpr int E_EDGES = 131072;
static constexpr int T_TRIP  = 1048576;
static constexpr int H_DIM   = 256;
static constexpr int I_DIM   = 64;
static constexpr int NR      = 6;
static constexpr int NSR     = 42;
static constexpr int BAS     = 8;

// ---------------- scratch (static device memory) ----------------
__device__ float g_xr  [(size_t)E_EDGES * H_DIM];
__device__ float g_xji [(size_t)E_EDGES * H_DIM];
__device__ float g_bufA[(size_t)E_EDGES * H_DIM];
__device__ float g_bufB[(size_t)E_EDGES * H_DIM];
__device__ float g_xkjd[(size_t)E_EDGES * I_DIM];
__device__ float g_agg [(size_t)E_EDGES * I_DIM];
__device__ float g_wr  [622592];   // tf32-rounded weights, concatenated

// weight offsets inside g_wr
static constexpr int WO_JI   = 0;
static constexpr int WO_KJ   = 65536;
static constexpr int WO_B11  = 131072;
static constexpr int WO_B12  = 196608;
static constexpr int WO_LIN  = 262144;
static constexpr int WO_A11  = 327680;
static constexpr int WO_A12  = 393216;
static constexpr int WO_A21  = 458752;
static constexpr int WO_A22  = 524288;
static constexpr int WO_DOWN = 589824;   // 256*64
static constexpr int WO_UP   = 606208;   // 64*256

// ---------------- helpers ----------------
__device__ __forceinline__ uint32_t smem_to_u32(const void* p) {
    uint32_t a;
    asm("{ .reg .u64 t; cvta.to.shared.u64 t, %1; cvt.u32.u64 %0, t; }" : "=r"(a) : "l"(p));
    return a;
}
__device__ __forceinline__ uint32_t tf32r(float v) {
    uint32_t o; asm("cvt.rna.tf32.f32 %0, %1;" : "=r"(o) : "f"(v)); return o;
}
__device__ __forceinline__ float silu_f(float v) {
    return v * (1.0f / (1.0f + __expf(-v)));
}
__device__ __forceinline__ void cp_async16(uint32_t dst, const void* src) {
    asm volatile("cp.async.cg.shared.global [%0], [%1], 16;" :: "r"(dst), "l"(src));
}
__device__ __forceinline__ void mma_tf32(float d[4], const uint32_t a[4], const uint32_t b[2]) {
    asm volatile(
        "mma.sync.aligned.m16n8k8.row.col.f32.tf32.tf32.f32 "
        "{%0,%1,%2,%3}, {%4,%5,%6,%7}, {%8,%9}, {%0,%1,%2,%3};"
        : "+f"(d[0]), "+f"(d[1]), "+f"(d[2]), "+f"(d[3])
        : "r"(a[0]), "r"(a[1]), "r"(a[2]), "r"(a[3]), "r"(b[0]), "r"(b[1]));
}

// ============ mma.sync tf32 GEMM: C = [res +] silu(A @ W [+ bias]) ============
// 128-thread CTA, 4 warps as 2M x 2N; warp tile 64 x (BN/2).
// Register-level fragment double-buffering: slab ks+1 fragments load while
// slab ks MMAs issue (CUTLASS sm80 pattern). LDS:MMA = 0.75 (was 1.5).
// BK=32, DEPTH=3 cp.async ring; A stride 36, B stride BN+8 (conflict-free).
template <int BN, int K>
__global__ void __launch_bounds__(128, 2)
mma_gemm(const float* __restrict__ A, const float* __restrict__ W,
         const float* __restrict__ bias, const float* __restrict__ res,
         float* __restrict__ C, int Nfull)
{
    constexpr int BM = 128, BK = 32, DEPTH = 3;
    constexpr int KT = K / BK;
    constexpr int AS_STRIDE = BK + 4;                 // 36: A-frag bank = 4g+q, distinct
    constexpr int AS_STAGE  = BM * AS_STRIDE;
    constexpr int BS_STRIDE = BN + 8;                 // 136/72: B-frag bank = 8q+g, distinct
    constexpr int BS_STAGE  = BK * BS_STRIDE;
    constexpr int NFW = BN / 16;                      // n8-frags per warp (8 / 4)

    extern __shared__ float smf[];
    float* As = smf;
    float* Bs = smf + DEPTH * AS_STAGE;
    const uint32_t smemA = smem_to_u32(As);
    const uint32_t smemB = smem_to_u32(Bs);

    const int tid = threadIdx.x, lane = tid & 31, wid = tid >> 5;
    const int warpM = wid >> 1, warpN = wid & 1;      // 2 x 2
    const int row0 = blockIdx.y * BM;
    const int col0 = blockIdx.x * BN;
    const int g = lane >> 2, q = lane & 3;

    float acc[4][NFW][4];
#pragma unroll
    for (int mf = 0; mf < 4; mf++)
#pragma unroll
        for (int nf = 0; nf < NFW; nf++)
#pragma unroll
            for (int v = 0; v < 4; v++) acc[mf][nf][v] = 0.0f;

    auto load_stage = [&](int s, int kt) {
        const int k0 = kt * BK;
        // A: 128x32 floats = 1024 16B chunks, 8 per thread
#pragma unroll
        for (int i = 0; i < 8; i++) {
            int id = tid + i * 128;
            int m = id >> 3, c4 = (id & 7) * 4;
            cp_async16(smemA + (uint32_t)(s * AS_STAGE + m * AS_STRIDE + c4) * 4,
                       A + (size_t)(row0 + m) * K + k0 + c4);
        }
        // B: 32 x BN floats
        constexpr int BCH = BK * BN / 4;
#pragma unroll
        for (int i = 0; i < BCH / 128; i++) {
            int id = tid + i * 128;
            int k = id / (BN / 4), n4 = (id % (BN / 4)) * 4;
            cp_async16(smemB + (uint32_t)(s * BS_STAGE + k * BS_STRIDE + n4) * 4,
                       W + (size_t)(k0 + k) * Nfull + col0 + n4);
        }
    };

#pragma unroll
    for (int s = 0; s < DEPTH - 1; s++) {
        if (s < KT) load_stage(s, s);
        asm volatile("cp.async.commit_group;" ::: "memory");
    }

    uint32_t af[2][4][4];     // [buf][mf][4]
    uint32_t bf[2][NFW][2];   // [buf][nf][2]

    for (int it = 0; it < KT; it++) {
        asm volatile("cp.async.wait_group %0;" :: "n"(DEPTH - 2) : "memory");
        __syncthreads();
        const int nx = it + DEPTH - 1;
        if (nx < KT) load_stage(nx % DEPTH, nx);
        asm volatile("cp.async.commit_group;" ::: "memory");

        const int s = it % DEPTH;
        const float* Asb = As + s * AS_STAGE;
        const float* Bsb = Bs + s * BS_STAGE;

        // prime slab-0 fragments
#pragma unroll
        for (int mf = 0; mf < 4; mf++) {
            int r = warpM * 64 + mf * 16 + g;
            af[0][mf][0] = __float_as_uint(Asb[r * AS_STRIDE + q]);
            af[0][mf][1] = __float_as_uint(Asb[(r + 8) * AS_STRIDE + q]);
            af[0][mf][2] = __float_as_uint(Asb[r * AS_STRIDE + q + 4]);
            af[0][mf][3] = __float_as_uint(Asb[(r + 8) * AS_STRIDE + q + 4]);
        }
#pragma unroll
        for (int nf = 0; nf < NFW; nf++) {
            int c = warpN * (BN / 2) + nf * 8 + g;
            bf[0][nf][0] = __float_as_uint(Bsb[q * BS_STRIDE + c]);
            bf[0][nf][1] = __float_as_uint(Bsb[(q + 4) * BS_STRIDE + c]);
        }

#pragma unroll
        for (int ks = 0; ks < 4; ks++) {
            const int cur = ks & 1, nxt = cur ^ 1;
            if (ks < 3) {
                const int kk = (ks + 1) * 8;
#pragma unroll
                for (int mf = 0; mf < 4; mf++) {
                    int r = warpM * 64 + mf * 16 + g;
                    af[nxt][mf][0] = __float_as_uint(Asb[r * AS_STRIDE + kk + q]);
                    af[nxt][mf][1] = __float_as_uint(Asb[(r + 8) * AS_STRIDE + kk + q]);
                    af[nxt][mf][2] = __float_as_uint(Asb[r * AS_STRIDE + kk + q + 4]);
                    af[nxt][mf][3] = __float_as_uint(Asb[(r + 8) * AS_STRIDE + kk + q + 4]);
                }
#pragma unroll
                for (int nf = 0; nf < NFW; nf++) {
                    int c = warpN * (BN / 2) + nf * 8 + g;
                    bf[nxt][nf][0] = __float_as_uint(Bsb[(kk + q) * BS_STRIDE + c]);
                    bf[nxt][nf][1] = __float_as_uint(Bsb[(kk + q + 4) * BS_STRIDE + c]);
                }
            }
#pragma unroll
            for (int mf = 0; mf < 4; mf++)
#pragma unroll
                for (int nf = 0; nf < NFW; nf++)
                    mma_tf32(acc[mf][nf], af[cur][mf], bf[cur][nf]);
        }
    }

    // epilogue: bias -> silu -> +res -> tf32-rounded store
#pragma unroll
    for (int mf = 0; mf < 4; mf++) {
#pragma unroll
        for (int nf = 0; nf < NFW; nf++) {
            const int col = col0 + warpN * (BN / 2) + nf * 8 + 2 * q;
            float bv0 = 0.0f, bv1 = 0.0f;
            if (bias) { bv0 = bias[col]; bv1 = bias[col + 1]; }
#pragma unroll
            for (int h = 0; h < 2; h++) {
                const int row = row0 + warpM * 64 + mf * 16 + g + h * 8;
                float v0 = silu_f(acc[mf][nf][h * 2 + 0] + bv0);
                float v1 = silu_f(acc[mf][nf][h * 2 + 1] + bv1);
                const size_t off = (size_t)row * Nfull + col;
                if (res) {
                    float2 r = *reinterpret_cast<const float2*>(res + off);
                    v0 += r.x; v1 += r.y;
                }
                uint2 o;
                o.x = tf32r(v0);
                o.y = tf32r(v1);
                *reinterpret_cast<uint2*>(C + off) = o;
            }
        }
    }
}

static constexpr int mma_smem(int BN) {
    return 3 * (128 * 36 + 32 * (BN + 8)) * 4;
}

// ---------------- round x to tf32-representable fp32 ----------------
__global__ void round_copy_kernel(const float4* __restrict__ in, float4* __restrict__ out, int n4)
{
    int i = blockIdx.x * blockDim.x + threadIdx.x;
    int stride = gridDim.x * blockDim.x;
    for (; i < n4; i += stride) {
        float4 v = in[i];
        uint4 o;
        o.x = tf32r(v.x); o.y = tf32r(v.y); o.z = tf32r(v.z); o.w = tf32r(v.w);
        *reinterpret_cast<uint4*>(&out[i]) = o;
    }
}

// ---------------- round all weights, one launch ----------------
struct WSet { const float* src[11]; float* dst[11]; int n4[11]; };
__global__ void round_w_kernel(WSet ws)
{
    int seg = blockIdx.y;
    const float4* s = reinterpret_cast<const float4*>(ws.src[seg]);
    float4* d = reinterpret_cast<float4*>(ws.dst[seg]);
    int n4 = ws.n4[seg];
    for (int i = blockIdx.x * blockDim.x + threadIdx.x; i < n4; i += gridDim.x * blockDim.x) {
        float4 v = s[i];
        uint4 o;
        o.x = tf32r(v.x); o.y = tf32r(v.y); o.z = tf32r(v.z); o.w = tf32r(v.w);
        *reinterpret_cast<uint4*>(&d[i]) = o;
    }
}

// ---------------- rbf gating: xkj[r,:] *= (rbf[r,:] @ W1) @ W2 ; tf32-rounded ----------------
__global__ void rbf_gate_kernel(float* __restrict__ xkj,
                                const float* __restrict__ rbf,
                                const float* __restrict__ W1,   // [6,8]
                                const float* __restrict__ W2)   // [8,256]
{
    __shared__ __align__(16) float sW2[BAS * H_DIM];
    __shared__ float sW1[NR * BAS];
    for (int i = threadIdx.x; i < BAS * H_DIM; i += blockDim.x) sW2[i] = W2[i];
    for (int i = threadIdx.x; i < NR * BAS; i += blockDim.x)    sW1[i] = W1[i];
    __syncthreads();

    const int lane  = threadIdx.x & 31;
    const int wglob = (blockIdx.x * blockDim.x + threadIdx.x) >> 5;
    const int nwarp = (gridDim.x * blockDim.x) >> 5;
    const int j = lane & 7;
    const int g = lane >> 3;

    for (int r = wglob; r < E_EDGES; r += nwarp) {
        float s = 0.f;
        for (int i = g; i < NR; i += 4) s += rbf[(size_t)r * NR + i] * sW1[i * BAS + j];
        s += __shfl_xor_sync(0xffffffffu, s, 8);
        s += __shfl_xor_sync(0xffffffffu, s, 16);
        int c = lane * 8;
        float4 g0 = make_float4(0, 0, 0, 0), g1 = make_float4(0, 0, 0, 0);
#pragma unroll
        for (int jj = 0; jj < BAS; jj++) {
            float sj = __shfl_sync(0xffffffffu, s, jj);
            float4 w0 = *reinterpret_cast<const float4*>(&sW2[jj * H_DIM + c]);
            float4 w1 = *reinterpret_cast<const float4*>(&sW2[jj * H_DIM + c + 4]);
            g0.x += sj * w0.x; g0.y += sj * w0.y; g0.z += sj * w0.z; g0.w += sj * w0.w;
            g1.x += sj * w1.x; g1.y += sj * w1.y; g1.z += sj * w1.z; g1.w += sj * w1.w;
        }
        float4* p0 = reinterpret_cast<float4*>(&xkj[(size_t)r * H_DIM + c]);
        float4* p1 = reinterpret_cast<float4*>(&xkj[(size_t)r * H_DIM + c + 4]);
        float4 x0 = *p0, x1 = *p1;
        uint4 o0, o1;
        o0.x = tf32r(x0.x * g0.x); o0.y = tf32r(x0.y * g0.y);
        o0.z = tf32r(x0.z * g0.z); o0.w = tf32r(x0.w * g0.w);
        o1.x = tf32r(x1.x * g1.x); o1.y = tf32r(x1.y * g1.y);
        o1.z = tf32r(x1.z * g1.z); o1.w = tf32r(x1.w * g1.w);
        *reinterpret_cast<uint4*>(p0) = o0;
        *reinterpret_cast<uint4*>(p1) = o1;
    }
}

// ---------------- zero scratch ----------------
__global__ void zero_kernel(float4* __restrict__ p, int n4)
{
    int i = blockIdx.x * blockDim.x + threadIdx.x;
    int stride = gridDim.x * blockDim.x;
    for (; i < n4; i += stride) p[i] = make_float4(0, 0, 0, 0);
}

// ---------------- triplet pass ----------------
__global__ void triplet_kernel(const float* __restrict__ sbf,
                               const int* __restrict__ idx_kj,
                               const int* __restrict__ idx_ji,
                               const float* __restrict__ W1,   // [42,8]
                               const float* __restrict__ W2,   // [8,64]
                               const float* __restrict__ xkjd, // [E,64]
                               float* __restrict__ agg)        // [E,64]
{
    __shared__ float sW1[NSR * BAS];
    __shared__ __align__(16) float sW2[BAS * I_DIM];
    for (int i = threadIdx.x; i < NSR * BAS; i += blockDim.x) sW1[i] = W1[i];
    for (int i = threadIdx.x; i < BAS * I_DIM; i += blockDim.x) sW2[i] = W2[i];
    __syncthreads();

    const int lane  = threadIdx.x & 31;
    const int wglob = (blockIdx.x * blockDim.x + threadIdx.x) >> 5;
    const int nwarp = (gridDim.x * blockDim.x) >> 5;
    const int sub = lane >> 4;
    const int sl  = lane & 15;
    const int j   = sl & 7;
    const int g   = sl >> 3;

    for (int p = wglob; p * 2 < T_TRIP; p += nwarp) {
        int t = p * 2 + sub;
        const float* srow = sbf + (size_t)t * NSR;
        float s = 0.f;
        for (int i = g; i < NSR; i += 2) s += srow[i] * sW1[i * BAS + j];
        s += __shfl_xor_sync(0xffffffffu, s, 8);

        int ekj = idx_kj[t];
        int eji = idx_ji[t];
        int c = sl * 4;
        float4 xv = *reinterpret_cast<const float4*>(&xkjd[(size_t)ekj * I_DIM + c]);
        float4 m = make_float4(0, 0, 0, 0);
#pragma unroll
        for (int jj = 0; jj < BAS; jj++) {
            float sj = __shfl_sync(0xffffffffu, s, (sub << 4) + jj);
            float4 w = *reinterpret_cast<const float4*>(&sW2[jj * I_DIM + c]);
            m.x += sj * w.x; m.y += sj * w.y; m.z += sj * w.z; m.w += sj * w.w;
        }
        m.x *= xv.x; m.y *= xv.y; m.z *= xv.z; m.w *= xv.w;
        atomicAdd(reinterpret_cast<float4*>(&agg[(size_t)eji * I_DIM + c]), m);
    }
}

// ---------------- launch ----------------
extern "C" void kernel_launch(void* const* d_in, const int* in_sizes, int n_in,
                              void* d_out, int out_size)
{
    const float* x      = (const float*)d_in[0];
    const float* rbf    = (const float*)d_in[1];
    const float* sbf    = (const float*)d_in[2];
    const int*   idx_kj = (const int*)d_in[3];
    const int*   idx_ji = (const int*)d_in[4];
    const float* W_ji   = (const float*)d_in[5];
    const float* b_ji   = (const float*)d_in[6];
    const float* W_kj   = (const float*)d_in[7];
    const float* b_kj   = (const float*)d_in[8];
    const float* W_rbf1 = (const float*)d_in[9];
    const float* W_rbf2 = (const float*)d_in[10];
    const float* W_sbf1 = (const float*)d_in[11];
    const float* W_sbf2 = (const float*)d_in[12];
    const float* W_down = (const float*)d_in[13];
    const float* W_up   = (const float*)d_in[14];
    const float* Wb1_1  = (const float*)d_in[15];
    const float* bb1_1  = (const float*)d_in[16];
    const float* Wb1_2  = (const float*)d_in[17];
    const float* bb1_2  = (const float*)d_in[18];
    const float* W_lin  = (const float*)d_in[19];
    const float* b_lin  = (const float*)d_in[20];
    const float* Wa1_1  = (const float*)d_in[21];
    const float* ba1_1  = (const float*)d_in[22];
    const float* Wa1_2  = (const float*)d_in[23];
    const float* ba1_2  = (const float*)d_in[24];
    const float* Wa2_1  = (const float*)d_in[25];
    const float* ba2_1  = (const float*)d_in[26];
    const float* Wa2_2  = (const float*)d_in[27];
    const float* ba2_2  = (const float*)d_in[28];
    float* out = (float*)d_out;

    float *xr, *xji, *bufA, *bufB, *xkjd, *agg, *wr;
    cudaGetSymbolAddress((void**)&xr,   g_xr);
    cudaGetSymbolAddress((void**)&xji,  g_xji);
    cudaGetSymbolAddress((void**)&bufA, g_bufA);
    cudaGetSymbolAddress((void**)&bufB, g_bufB);
    cudaGetSymbolAddress((void**)&xkjd, g_xkjd);
    cudaGetSymbolAddress((void**)&agg,  g_agg);
    cudaGetSymbolAddress((void**)&wr,   g_wr);

    constexpr int SM_BIG  = mma_smem(128);   // 107,520 B -> occ 2 (215 KB/SM)
    constexpr int SM_DOWN = mma_smem(64);
    cudaFuncSetAttribute(mma_gemm<128, 256>, cudaFuncAttributeMaxDynamicSharedMemorySize, SM_BIG);
    cudaFuncSetAttribute(mma_gemm<64, 256>,  cudaFuncAttributeMaxDynamicSharedMemorySize, SM_DOWN);
    cudaFuncSetAttribute(mma_gemm<128, 64>,  cudaFuncAttributeMaxDynamicSharedMemorySize, SM_BIG);

    const dim3 gBig(2, E_EDGES / 128);   // x = N-tile (fast) -> A-tile L2 reuse
    const dim3 gDown(1, E_EDGES / 128);

    // 0: round x
    round_copy_kernel<<<1024, 256>>>((const float4*)x, (float4*)xr, E_EDGES * H_DIM / 4);

    // 1: round all weights (single launch)
    WSet ws;
    const float* srcs[11] = {W_ji, W_kj, Wb1_1, Wb1_2, W_lin, Wa1_1, Wa1_2, Wa2_1, Wa2_2, W_down, W_up};
    const int offs[11]    = {WO_JI, WO_KJ, WO_B11, WO_B12, WO_LIN, WO_A11, WO_A12, WO_A21, WO_A22, WO_DOWN, WO_UP};
    const int n4s[11]     = {16384, 16384, 16384, 16384, 16384, 16384, 16384, 16384, 16384, 4096, 4096};
    for (int i = 0; i < 11; i++) { ws.src[i] = srcs[i]; ws.dst[i] = wr + offs[i]; ws.n4[i] = n4s[i]; }
    round_w_kernel<<<dim3(16, 11), 256>>>(ws);

    // 2: x_ji = silu(x@W_ji + b)
    mma_gemm<128, 256><<<gBig, 128, SM_BIG>>>(xr, wr + WO_JI, b_ji, nullptr, xji, H_DIM);
    // 3: x_kj = silu(x@W_kj + b)
    mma_gemm<128, 256><<<gBig, 128, SM_BIG>>>(xr, wr + WO_KJ, b_kj, nullptr, bufA, H_DIM);
    // 4: gate
    rbf_gate_kernel<<<2048, 256>>>(bufA, rbf, W_rbf1, W_rbf2);
    // 5: x_kj_down = silu((x_kj*g) @ W_down)
    mma_gemm<64, 256><<<gDown, 128, SM_DOWN>>>(bufA, wr + WO_DOWN, nullptr, nullptr, xkjd, I_DIM);
    // 6: zero agg
    zero_kernel<<<1024, 256>>>((float4*)agg, E_EDGES * I_DIM / 4);
    // 7: triplet message passing
    triplet_kernel<<<2048, 256>>>(sbf, idx_kj, idx_ji, W_sbf1, W_sbf2, xkjd, agg);
    // 8: h = x_ji + silu(agg @ W_up)
    mma_gemm<128, 64><<<gBig, 128, SM_BIG>>>(agg, wr + WO_UP, nullptr, xji, bufA, H_DIM);
    // 9-10: pre-skip residual pair
    mma_gemm<128, 256><<<gBig, 128, SM_BIG>>>(bufA, wr + WO_B11, bb1_1, nullptr, bufB, H_DIM);
    mma_gemm<128, 256><<<gBig, 128, SM_BIG>>>(bufB, wr + WO_B12, bb1_2, bufA, bufA, H_DIM);
    // 11: skip: h = silu(h@W_lin+b) + x
    mma_gemm<128, 256><<<gBig, 128, SM_BIG>>>(bufA, wr + WO_LIN, b_lin, x, bufB, H_DIM);
    // 12-13: post-skip residual pair 1
    mma_gemm<128, 256><<<gBig, 128, SM_BIG>>>(bufB, wr + WO_A11, ba1_1, nullptr, bufA, H_DIM);
    mma_gemm<128, 256><<<gBig, 128, SM_BIG>>>(bufA, wr + WO_A12, ba1_2, bufB, bufB, H_DIM);
    // 14-15: post-skip residual pair 2 -> final output
    mma_gemm<128, 256><<<gBig, 128, SM_BIG>>>(bufB, wr + WO_A21, ba2_1, nullptr, bufA, H_DIM);
    mma_gemm<128, 256><<<gBig, 128, SM_BIG>>>(bufA, wr + WO_A22, ba2_2, bufB, out, H_DIM);
}

// round 11
// speedup vs baseline: 1.3604x; 1.3604x over previous
#include <cuda_runtime.h>
#include <cstdint>
#include <cstddef>

// ---------------- problem constants ----------------
static constexpr int E_EDGES = 131072;
static constexpr int T_TRIP  = 1048576;
static constexpr int H_DIM   = 256;
static constexpr int I_DIM   = 64;
static constexpr int NR      = 6;
static constexpr int NSR     = 42;
static constexpr int BAS     = 8;

// ---------------- scratch (static device memory) ----------------
__device__ float g_xr  [(size_t)E_EDGES * H_DIM];
__device__ float g_xji [(size_t)E_EDGES * H_DIM];
__device__ float g_bufA[(size_t)E_EDGES * H_DIM];
__device__ float g_bufB[(size_t)E_EDGES * H_DIM];
__device__ float g_xkjd[(size_t)E_EDGES * I_DIM];
__device__ float g_agg [(size_t)E_EDGES * I_DIM];
__device__ float g_s8t [(size_t)T_TRIP * BAS];      // sbf @ W_sbf1  [T,8]
__device__ float g_wr  [622592];   // tf32-rounded weights, concatenated

// weight offsets inside g_wr
static constexpr int WO_JI   = 0;
static constexpr int WO_KJ   = 65536;
static constexpr int WO_B11  = 131072;
static constexpr int WO_B12  = 196608;
static constexpr int WO_LIN  = 262144;
static constexpr int WO_A11  = 327680;
static constexpr int WO_A12  = 393216;
static constexpr int WO_A21  = 458752;
static constexpr int WO_A22  = 524288;
static constexpr int WO_DOWN = 589824;   // 256*64
static constexpr int WO_UP   = 606208;   // 64*256

// ---------------- helpers ----------------
__device__ __forceinline__ uint32_t smem_to_u32(const void* p) {
    uint32_t a;
    asm("{ .reg .u64 t; cvta.to.shared.u64 t, %1; cvt.u32.u64 %0, t; }" : "=r"(a) : "l"(p));
    return a;
}
__device__ __forceinline__ uint32_t tf32r(float v) {
    uint32_t o; asm("cvt.rna.tf32.f32 %0, %1;" : "=r"(o) : "f"(v)); return o;
}
__device__ __forceinline__ float silu_f(float v) {
    return v * (1.0f / (1.0f + __expf(-v)));
}
__device__ __forceinline__ void cp_async16(uint32_t dst, const void* src) {
    asm volatile("cp.async.cg.shared.global [%0], [%1], 16;" :: "r"(dst), "l"(src));
}
__device__ __forceinline__ void mma_tf32(float d[4], const uint32_t a[4], const uint32_t b[2]) {
    asm volatile(
        "mma.sync.aligned.m16n8k8.row.col.f32.tf32.tf32.f32 "
        "{%0,%1,%2,%3}, {%4,%5,%6,%7}, {%8,%9}, {%0,%1,%2,%3};"
        : "+f"(d[0]), "+f"(d[1]), "+f"(d[2]), "+f"(d[3])
        : "r"(a[0]), "r"(a[1]), "r"(a[2]), "r"(a[3]), "r"(b[0]), "r"(b[1]));
}

// ============ mma.sync tf32 GEMM (R9 proven config — DO NOT TOUCH) ============
// 256 threads, 8 warps (4M x 2N), warp tile 32 x BN/2, BK=32, DEPTH=3, occ 2.
template <int BN, int K>
__global__ void __launch_bounds__(256, 2)
mma_gemm(const float* __restrict__ A, const float* __restrict__ W,
         const float* __restrict__ bias, const float* __restrict__ res,
         float* __restrict__ C, int Nfull)
{
    constexpr int BM = 128, BK = 32, DEPTH = 3;
    constexpr int KT = K / BK;
    constexpr int AS_STRIDE = BK + 4;                 // 36
    constexpr int AS_STAGE  = BM * AS_STRIDE;
    constexpr int BS_STRIDE = BN + 8;                 // 136 / 72
    constexpr int BS_STAGE  = BK * BS_STRIDE;
    constexpr int NF = BN / 16;

    extern __shared__ float smf[];
    float* As = smf;
    float* Bs = smf + DEPTH * AS_STAGE;
    const uint32_t smemA = smem_to_u32(As);
    const uint32_t smemB = smem_to_u32(Bs);

    const int tid = threadIdx.x, lane = tid & 31, wid = tid >> 5;
    const int warpM = wid >> 1, warpN = wid & 1;
    const int row0 = blockIdx.y * BM;
    const int col0 = blockIdx.x * BN;
    const int g = lane >> 2, q = lane & 3;

    float acc[2][NF][4];
#pragma unroll
    for (int mf = 0; mf < 2; mf++)
#pragma unroll
        for (int nf = 0; nf < NF; nf++)
#pragma unroll
            for (int v = 0; v < 4; v++) acc[mf][nf][v] = 0.0f;

    auto load_stage = [&](int s, int kt) {
        const int k0 = kt * BK;
#pragma unroll
        for (int i = 0; i < 4; i++) {
            int id = tid + i * 256;
            int m = id >> 3, c4 = (id & 7) * 4;
            cp_async16(smemA + (uint32_t)(s * AS_STAGE + m * AS_STRIDE + c4) * 4,
                       A + (size_t)(row0 + m) * K + k0 + c4);
        }
        constexpr int BCH = BK * BN / 4;
#pragma unroll
        for (int i = 0; i < BCH / 256; i++) {
            int id = tid + i * 256;
            int k = id / (BN / 4), n4 = (id % (BN / 4)) * 4;
            cp_async16(smemB + (uint32_t)(s * BS_STAGE + k * BS_STRIDE + n4) * 4,
                       W + (size_t)(k0 + k) * Nfull + col0 + n4);
        }
    };

#pragma unroll
    for (int s = 0; s < DEPTH - 1; s++) {
        if (s < KT) load_stage(s, s);
        asm volatile("cp.async.commit_group;" ::: "memory");
    }

    for (int it = 0; it < KT; it++) {
        asm volatile("cp.async.wait_group %0;" :: "n"(DEPTH - 2) : "memory");
        __syncthreads();
        const int nx = it + DEPTH - 1;
        if (nx < KT) load_stage(nx % DEPTH, nx);
        asm volatile("cp.async.commit_group;" ::: "memory");

        const int s = it % DEPTH;
        const float* Asb = As + s * AS_STAGE;
        const float* Bsb = Bs + s * BS_STAGE;
#pragma unroll
        for (int ks = 0; ks < 4; ks++) {
            uint32_t af[2][4];
            uint32_t bf[NF][2];
#pragma unroll
            for (int mf = 0; mf < 2; mf++) {
                int r = warpM * 32 + mf * 16 + g;
                af[mf][0] = __float_as_uint(Asb[r * AS_STRIDE + ks * 8 + q]);
                af[mf][1] = __float_as_uint(Asb[(r + 8) * AS_STRIDE + ks * 8 + q]);
                af[mf][2] = __float_as_uint(Asb[r * AS_STRIDE + ks * 8 + q + 4]);
                af[mf][3] = __float_as_uint(Asb[(r + 8) * AS_STRIDE + ks * 8 + q + 4]);
            }
#pragma unroll
            for (int nf = 0; nf < NF; nf++) {
                int c = warpN * (BN / 2) + nf * 8 + g;
                bf[nf][0] = __float_as_uint(Bsb[(ks * 8 + q) * BS_STRIDE + c]);
                bf[nf][1] = __float_as_uint(Bsb[(ks * 8 + q + 4) * BS_STRIDE + c]);
            }
#pragma unroll
            for (int mf = 0; mf < 2; mf++)
#pragma unroll
                for (int nf = 0; nf < NF; nf++)
                    mma_tf32(acc[mf][nf], af[mf], bf[nf]);
        }
    }

#pragma unroll
    for (int mf = 0; mf < 2; mf++) {
#pragma unroll
        for (int nf = 0; nf < NF; nf++) {
            const int col = col0 + warpN * (BN / 2) + nf * 8 + 2 * q;
            float bv0 = 0.0f, bv1 = 0.0f;
            if (bias) { bv0 = bias[col]; bv1 = bias[col + 1]; }
#pragma unroll
            for (int h = 0; h < 2; h++) {
                const int row = row0 + warpM * 32 + mf * 16 + g + h * 8;
                float v0 = silu_f(acc[mf][nf][h * 2 + 0] + bv0);
                float v1 = silu_f(acc[mf][nf][h * 2 + 1] + bv1);
                const size_t off = (size_t)row * Nfull + col;
                if (res) {
                    float2 r = *reinterpret_cast<const float2*>(res + off);
                    v0 += r.x; v1 += r.y;
                }
                uint2 o;
                o.x = tf32r(v0);
                o.y = tf32r(v1);
                *reinterpret_cast<uint2*>(C + off) = o;
            }
        }
    }
}

static constexpr int mma_smem(int BN) {
    return 3 * (128 * 36 + 32 * (BN + 8)) * 4;
}

// ---------------- round x to tf32-representable fp32 ----------------
__global__ void round_copy_kernel(const float4* __restrict__ in, float4* __restrict__ out, int n4)
{
    int i = blockIdx.x * blockDim.x + threadIdx.x;
    int stride = gridDim.x * blockDim.x;
    for (; i < n4; i += stride) {
        float4 v = in[i];
        uint4 o;
        o.x = tf32r(v.x); o.y = tf32r(v.y); o.z = tf32r(v.z); o.w = tf32r(v.w);
        *reinterpret_cast<uint4*>(&out[i]) = o;
    }
}

// ---------------- round all weights, one launch ----------------
struct WSet { const float* src[11]; float* dst[11]; int n4[11]; };
__global__ void round_w_kernel(WSet ws)
{
    int seg = blockIdx.y;
    const float4* s = reinterpret_cast<const float4*>(ws.src[seg]);
    float4* d = reinterpret_cast<float4*>(ws.dst[seg]);
    int n4 = ws.n4[seg];
    for (int i = blockIdx.x * blockDim.x + threadIdx.x; i < n4; i += gridDim.x * blockDim.x) {
        float4 v = s[i];
        uint4 o;
        o.x = tf32r(v.x); o.y = tf32r(v.y); o.z = tf32r(v.z); o.w = tf32r(v.w);
        *reinterpret_cast<uint4*>(&d[i]) = o;
    }
}

// ---------------- s8t = sbf @ W_sbf1 : [T, 8] (coalesced precompute) ----------------
__global__ void s42_kernel(const float* __restrict__ sbf, const float* __restrict__ W1,
                           float* __restrict__ s8out)
{
    __shared__ float w[NSR * BAS];
    for (int i = threadIdx.x; i < NSR * BAS; i += blockDim.x) w[i] = W1[i];
    __syncthreads();
    int t = blockIdx.x * blockDim.x + threadIdx.x;
    const float* srow = sbf + (size_t)t * NSR;
    float o[BAS];
#pragma unroll
    for (int j = 0; j < BAS; j++) o[j] = 0.0f;
#pragma unroll
    for (int i = 0; i < NSR; i++) {
        float r = __ldg(srow + i);
#pragma unroll
        for (int j = 0; j < BAS; j++) o[j] += r * w[i * BAS + j];
    }
    float4 o0 = make_float4(o[0], o[1], o[2], o[3]);
    float4 o1 = make_float4(o[4], o[5], o[6], o[7]);
    reinterpret_cast<float4*>(s8out)[(size_t)t * 2 + 0] = o0;
    reinterpret_cast<float4*>(s8out)[(size_t)t * 2 + 1] = o1;
}

// ---------------- rbf gating: xkj[r,:] *= (rbf[r,:] @ W1) @ W2 ; tf32-rounded ----------------
__global__ void rbf_gate_kernel(float* __restrict__ xkj,
                                const float* __restrict__ rbf,
                                const float* __restrict__ W1,   // [6,8]
                                const float* __restrict__ W2)   // [8,256]
{
    __shared__ __align__(16) float sW2[BAS * H_DIM];
    __shared__ float sW1[NR * BAS];
    for (int i = threadIdx.x; i < BAS * H_DIM; i += blockDim.x) sW2[i] = W2[i];
    for (int i = threadIdx.x; i < NR * BAS; i += blockDim.x)    sW1[i] = W1[i];
    __syncthreads();

    const int lane  = threadIdx.x & 31;
    const int wglob = (blockIdx.x * blockDim.x + threadIdx.x) >> 5;
    const int nwarp = (gridDim.x * blockDim.x) >> 5;
    const int j = lane & 7;
    const int g = lane >> 3;

    for (int r = wglob; r < E_EDGES; r += nwarp) {
        float s = 0.f;
        for (int i = g; i < NR; i += 4) s += rbf[(size_t)r * NR + i] * sW1[i * BAS + j];
        s += __shfl_xor_sync(0xffffffffu, s, 8);
        s += __shfl_xor_sync(0xffffffffu, s, 16);
        int c = lane * 8;
        float4 g0 = make_float4(0, 0, 0, 0), g1 = make_float4(0, 0, 0, 0);
#pragma unroll
        for (int jj = 0; jj < BAS; jj++) {
            float sj = __shfl_sync(0xffffffffu, s, jj);
            float4 w0 = *reinterpret_cast<const float4*>(&sW2[jj * H_DIM + c]);
            float4 w1 = *reinterpret_cast<const float4*>(&sW2[jj * H_DIM + c + 4]);
            g0.x += sj * w0.x; g0.y += sj * w0.y; g0.z += sj * w0.z; g0.w += sj * w0.w;
            g1.x += sj * w1.x; g1.y += sj * w1.y; g1.z += sj * w1.z; g1.w += sj * w1.w;
        }
        float4* p0 = reinterpret_cast<float4*>(&xkj[(size_t)r * H_DIM + c]);
        float4* p1 = reinterpret_cast<float4*>(&xkj[(size_t)r * H_DIM + c + 4]);
        float4 x0 = *p0, x1 = *p1;
        uint4 o0, o1;
        o0.x = tf32r(x0.x * g0.x); o0.y = tf32r(x0.y * g0.y);
        o0.z = tf32r(x0.z * g0.z); o0.w = tf32r(x0.w * g0.w);
        o1.x = tf32r(x1.x * g1.x); o1.y = tf32r(x1.y * g1.y);
        o1.z = tf32r(x1.z * g1.z); o1.w = tf32r(x1.w * g1.w);
        *reinterpret_cast<uint4*>(p0) = o0;
        *reinterpret_cast<uint4*>(p1) = o1;
    }
}

// ---------------- zero scratch ----------------
__global__ void zero_kernel(float4* __restrict__ p, int n4)
{
    int i = blockIdx.x * blockDim.x + threadIdx.x;
    int stride = gridDim.x * blockDim.x;
    for (; i < n4; i += stride) p[i] = make_float4(0, 0, 0, 0);
}

// ---------------- triplet pass v2: uses precomputed s8t ----------------
// half-warp (16 lanes) per triplet; m = xkjd[idx_kj] * (s8t @ W2); agg[idx_ji] += m
__global__ void triplet_kernel(const float* __restrict__ s8t,  // [T,8]
                               const int* __restrict__ idx_kj,
                               const int* __restrict__ idx_ji,
                               const float* __restrict__ W2,   // [8,64]
                               const float* __restrict__ xkjd, // [E,64]
                               float* __restrict__ agg)        // [E,64]
{
    __shared__ __align__(16) float sW2[BAS * I_DIM]; // 2 KB
    for (int i = threadIdx.x; i < BAS * I_DIM; i += blockDim.x) sW2[i] = W2[i];
    __syncthreads();

    const int lane  = threadIdx.x & 31;
    const int wglob = (blockIdx.x * blockDim.x + threadIdx.x) >> 5;
    const int nwarp = (gridDim.x * blockDim.x) >> 5;
    const int sub = lane >> 4;   // which triplet of the pair
    const int sl  = lane & 15;
    const int c   = sl * 4;      // 4 cols per lane, 16 lanes = 64

    for (int p = wglob; p * 2 < T_TRIP; p += nwarp) {
        int t = p * 2 + sub;
        // broadcast loads of the 8 precomputed s-values
        const float4* s8p = reinterpret_cast<const float4*>(s8t + (size_t)t * BAS);
        float4 slo = __ldg(s8p + 0);
        float4 shi = __ldg(s8p + 1);
        int ekj = __ldg(idx_kj + t);
        int eji = __ldg(idx_ji + t);
        float4 xv = *reinterpret_cast<const float4*>(&xkjd[(size_t)ekj * I_DIM + c]);

        float4 m = make_float4(0, 0, 0, 0);
        const float4* w0 = reinterpret_cast<const float4*>(&sW2[0 * I_DIM + c]);
#pragma unroll
        for (int jj = 0; jj < 4; jj++) {
            float sj = (jj == 0) ? slo.x : (jj == 1) ? slo.y : (jj == 2) ? slo.z : slo.w;
            float4 w = *reinterpret_cast<const float4*>(&sW2[jj * I_DIM + c]);
            m.x += sj * w.x; m.y += sj * w.y; m.z += sj * w.z; m.w += sj * w.w;
        }
#pragma unroll
        for (int jj = 0; jj < 4; jj++) {
            float sj = (jj == 0) ? shi.x : (jj == 1) ? shi.y : (jj == 2) ? shi.z : shi.w;
            float4 w = *reinterpret_cast<const float4*>(&sW2[(jj + 4) * I_DIM + c]);
            m.x += sj * w.x; m.y += sj * w.y; m.z += sj * w.z; m.w += sj * w.w;
        }
        m.x *= xv.x; m.y *= xv.y; m.z *= xv.z; m.w *= xv.w;
        atomicAdd(reinterpret_cast<float4*>(&agg[(size_t)eji * I_DIM + c]), m);
        (void)w0;
    }
}

// ---------------- launch ----------------
extern "C" void kernel_launch(void* const* d_in, const int* in_sizes, int n_in,
                              void* d_out, int out_size)
{
    const float* x      = (const float*)d_in[0];
    const float* rbf    = (const float*)d_in[1];
    const float* sbf    = (const float*)d_in[2];
    const int*   idx_kj = (const int*)d_in[3];
    const int*   idx_ji = (const int*)d_in[4];
    const float* W_ji   = (const float*)d_in[5];
    const float* b_ji   = (const float*)d_in[6];
    const float* W_kj   = (const float*)d_in[7];
    const float* b_kj   = (const float*)d_in[8];
    const float* W_rbf1 = (const float*)d_in[9];
    const float* W_rbf2 = (const float*)d_in[10];
    const float* W_sbf1 = (const float*)d_in[11];
    const float* W_sbf2 = (const float*)d_in[12];
    const float* W_down = (const float*)d_in[13];
    const float* W_up   = (const float*)d_in[14];
    const float* Wb1_1  = (const float*)d_in[15];
    const float* bb1_1  = (const float*)d_in[16];
    const float* Wb1_2  = (const float*)d_in[17];
    const float* bb1_2  = (const float*)d_in[18];
    const float* W_lin  = (const float*)d_in[19];
    const float* b_lin  = (const float*)d_in[20];
    const float* Wa1_1  = (const float*)d_in[21];
    const float* ba1_1  = (const float*)d_in[22];
    const float* Wa1_2  = (const float*)d_in[23];
    const float* ba1_2  = (const float*)d_in[24];
    const float* Wa2_1  = (const float*)d_in[25];
    const float* ba2_1  = (const float*)d_in[26];
    const float* Wa2_2  = (const float*)d_in[27];
    const float* ba2_2  = (const float*)d_in[28];
    float* out = (float*)d_out;

    float *xr, *xji, *bufA, *bufB, *xkjd, *agg, *s8t, *wr;
    cudaGetSymbolAddress((void**)&xr,   g_xr);
    cudaGetSymbolAddress((void**)&xji,  g_xji);
    cudaGetSymbolAddress((void**)&bufA, g_bufA);
    cudaGetSymbolAddress((void**)&bufB, g_bufB);
    cudaGetSymbolAddress((void**)&xkjd, g_xkjd);
    cudaGetSymbolAddress((void**)&agg,  g_agg);
    cudaGetSymbolAddress((void**)&s8t,  g_s8t);
    cudaGetSymbolAddress((void**)&wr,   g_wr);

    constexpr int SM_BIG  = mma_smem(128);   // 107,520 B -> occ 2
    constexpr int SM_DOWN = mma_smem(64);
    cudaFuncSetAttribute(mma_gemm<128, 256>, cudaFuncAttributeMaxDynamicSharedMemorySize, SM_BIG);
    cudaFuncSetAttribute(mma_gemm<64, 256>,  cudaFuncAttributeMaxDynamicSharedMemorySize, SM_DOWN);
    cudaFuncSetAttribute(mma_gemm<128, 64>,  cudaFuncAttributeMaxDynamicSharedMemorySize, SM_BIG);

    const dim3 gBig(2, E_EDGES / 128);
    const dim3 gDown(1, E_EDGES / 128);

    // 0: round x
    round_copy_kernel<<<1024, 256>>>((const float4*)x, (float4*)xr, E_EDGES * H_DIM / 4);

    // 1: round all weights (single launch)
    WSet ws;
    const float* srcs[11] = {W_ji, W_kj, Wb1_1, Wb1_2, W_lin, Wa1_1, Wa1_2, Wa2_1, Wa2_2, W_down, W_up};
    const int offs[11]    = {WO_JI, WO_KJ, WO_B11, WO_B12, WO_LIN, WO_A11, WO_A12, WO_A21, WO_A22, WO_DOWN, WO_UP};
    const int n4s[11]     = {16384, 16384, 16384, 16384, 16384, 16384, 16384, 16384, 16384, 4096, 4096};
    for (int i = 0; i < 11; i++) { ws.src[i] = srcs[i]; ws.dst[i] = wr + offs[i]; ws.n4[i] = n4s[i]; }
    round_w_kernel<<<dim3(16, 11), 256>>>(ws);

    // 2: s8t = sbf @ W_sbf1   (coalesced precompute, independent of GEMMs)
    s42_kernel<<<T_TRIP / 256, 256>>>(sbf, W_sbf1, s8t);
    // 3: x_kj = silu(x@W_kj + b)
    mma_gemm<128, 256><<<gBig, 256, SM_BIG>>>(xr, wr + WO_KJ, b_kj, nullptr, bufA, H_DIM);
    // 4: gate
    rbf_gate_kernel<<<2048, 256>>>(bufA, rbf, W_rbf1, W_rbf2);
    // 5: x_kj_down = silu((x_kj*g) @ W_down)   <- ncu slot 5: down-GEMM profile
    mma_gemm<64, 256><<<gDown, 256, SM_DOWN>>>(bufA, wr + WO_DOWN, nullptr, nullptr, xkjd, I_DIM);
    // 6: zero agg
    zero_kernel<<<1024, 256>>>((float4*)agg, E_EDGES * I_DIM / 4);
    // 7: triplet message passing (v2, lean)
    triplet_kernel<<<2048, 256>>>(s8t, idx_kj, idx_ji, W_sbf2, xkjd, agg);
    // 8: x_ji = silu(x@W_ji + b)
    mma_gemm<128, 256><<<gBig, 256, SM_BIG>>>(xr, wr + WO_JI, b_ji, nullptr, xji, H_DIM);
    // 9: h = x_ji + silu(agg @ W_up)
    mma_gemm<128, 64><<<gBig, 256, SM_BIG>>>(agg, wr + WO_UP, nullptr, xji, bufA, H_DIM);
    // 10-11: pre-skip residual pair
    mma_gemm<128, 256><<<gBig, 256, SM_BIG>>>(bufA, wr + WO_B11, bb1_1, nullptr, bufB, H_DIM);
    mma_gemm<128, 256><<<gBig, 256, SM_BIG>>>(bufB, wr + WO_B12, bb1_2, bufA, bufA, H_DIM);
    // 12: skip: h = silu(h@W_lin+b) + x
    mma_gemm<128, 256><<<gBig, 256, SM_BIG>>>(bufA, wr + WO_LIN, b_lin, x, bufB, H_DIM);
    // 13-14: post-skip residual pair 1
    mma_gemm<128, 256><<<gBig, 256, SM_BIG>>>(bufB, wr + WO_A11, ba1_1, nullptr, bufA, H_DIM);
    mma_gemm<128, 256><<<gBig, 256, SM_BIG>>>(bufA, wr + WO_A12, ba1_2, bufB, bufB, H_DIM);
    // 15-16: post-skip residual pair 2 -> final output
    mma_gemm<128, 256><<<gBig, 256, SM_BIG>>>(bufB, wr + WO_A21, ba2_1, nullptr, bufA, H_DIM);
    mma_gemm<128, 256><<<gBig, 256, SM_BIG>>>(bufA, wr + WO_A22, ba2_2, bufB, out, H_DIM);
}

// round 12
// speedup vs baseline: 1.4027x; 1.0311x over previous
#include <cuda_runtime.h>
#include <cstdint>
#include <cstddef>

// ---------------- problem constants ----------------
static constexpr int E_EDGES = 131072;
static constexpr int T_TRIP  = 1048576;
static constexpr int H_DIM   = 256;
static constexpr int I_DIM   = 64;
static constexpr int NR      = 6;
static constexpr int NSR     = 42;
static constexpr int BAS     = 8;

// ---------------- scratch (static device memory) ----------------
__device__ float g_xji [(size_t)E_EDGES * H_DIM];
__device__ float g_bufA[(size_t)E_EDGES * H_DIM];
__device__ float g_bufB[(size_t)E_EDGES * H_DIM];
__device__ float g_xkjd[(size_t)E_EDGES * I_DIM];
__device__ float g_agg [(size_t)E_EDGES * I_DIM];
__device__ float g_s8t [(size_t)T_TRIP * BAS];      // sbf @ W_sbf1  [T,8]
__device__ float g_s8e [(size_t)E_EDGES * BAS];     // rbf @ W_rbf1  [E,8]
__device__ float g_wr  [622592];   // tf32-rounded weights, concatenated

// weight offsets inside g_wr
static constexpr int WO_JI   = 0;
static constexpr int WO_KJ   = 65536;
static constexpr int WO_B11  = 131072;
static constexpr int WO_B12  = 196608;
static constexpr int WO_LIN  = 262144;
static constexpr int WO_A11  = 327680;
static constexpr int WO_A12  = 393216;
static constexpr int WO_A21  = 458752;
static constexpr int WO_A22  = 524288;
static constexpr int WO_DOWN = 589824;   // 256*64
static constexpr int WO_UP   = 606208;   // 64*256

// ---------------- helpers ----------------
__device__ __forceinline__ uint32_t smem_to_u32(const void* p) {
    uint32_t a;
    asm("{ .reg .u64 t; cvta.to.shared.u64 t, %1; cvt.u32.u64 %0, t; }" : "=r"(a) : "l"(p));
    return a;
}
__device__ __forceinline__ uint32_t tf32r(float v) {
    uint32_t o; asm("cvt.rna.tf32.f32 %0, %1;" : "=r"(o) : "f"(v)); return o;
}
__device__ __forceinline__ uint32_t tf32r_u(uint32_t v) {
    uint32_t o; asm("cvt.rna.tf32.f32 %0, %1;" : "=r"(o) : "r"(v)); return o;
}
__device__ __forceinline__ float silu_f(float v) {
    return v * (1.0f / (1.0f + __expf(-v)));
}
__device__ __forceinline__ void cp_async16(uint32_t dst, const void* src) {
    asm volatile("cp.async.cg.shared.global [%0], [%1], 16;" :: "r"(dst), "l"(src));
}
__device__ __forceinline__ void mma_tf32(float d[4], const uint32_t a[4], const uint32_t b[2]) {
    asm volatile(
        "mma.sync.aligned.m16n8k8.row.col.f32.tf32.tf32.f32 "
        "{%0,%1,%2,%3}, {%4,%5,%6,%7}, {%8,%9}, {%0,%1,%2,%3};"
        : "+f"(d[0]), "+f"(d[1]), "+f"(d[2]), "+f"(d[3])
        : "r"(a[0]), "r"(a[1]), "r"(a[2]), "r"(a[3]), "r"(b[0]), "r"(b[1]));
}

// ============ mma.sync tf32 GEMM (R9 core) with epilogue fusions ============
// GATE: out = silu(acc+bias) * (s8e[row] @ Wg[:,col]); RA: round A-frags to tf32 in-register.
// 256 threads, 8 warps (4M x 2N), warp tile 32 x BN/2, BK=32, DEPTH=3, occ 2.
template <int BN, int K, int GATE, int RA>
__global__ void __launch_bounds__(256, 2)
mma_gemm(const float* __restrict__ A, const float* __restrict__ W,
         const float* __restrict__ bias, const float* __restrict__ res,
         float* __restrict__ C, int Nfull,
         const float* __restrict__ s8e, const float* __restrict__ Wg)
{
    constexpr int BM = 128, BK = 32, DEPTH = 3;
    constexpr int KT = K / BK;
    constexpr int AS_STRIDE = BK + 4;                 // 36
    constexpr int AS_STAGE  = BM * AS_STRIDE;
    constexpr int BS_STRIDE = BN + 8;                 // 136 / 72
    constexpr int BS_STAGE  = BK * BS_STRIDE;
    constexpr int NF = BN / 16;

    extern __shared__ float smf[];
    float* As = smf;
    float* Bs = smf + DEPTH * AS_STAGE;
    float* gWs = Bs + DEPTH * BS_STAGE;               // [8][BN], GATE only
    const uint32_t smemA = smem_to_u32(As);
    const uint32_t smemB = smem_to_u32(Bs);

    const int tid = threadIdx.x, lane = tid & 31, wid = tid >> 5;
    const int warpM = wid >> 1, warpN = wid & 1;
    const int row0 = blockIdx.y * BM;
    const int col0 = blockIdx.x * BN;
    const int g = lane >> 2, q = lane & 3;

    if (GATE) {
        for (int i = tid; i < BAS * BN; i += 256) {
            int j = i / BN, n = i % BN;
            gWs[j * BN + n] = Wg[j * Nfull + col0 + n];
        }
    }

    float acc[2][NF][4];
#pragma unroll
    for (int mf = 0; mf < 2; mf++)
#pragma unroll
        for (int nf = 0; nf < NF; nf++)
#pragma unroll
            for (int v = 0; v < 4; v++) acc[mf][nf][v] = 0.0f;

    auto load_stage = [&](int s, int kt) {
        const int k0 = kt * BK;
#pragma unroll
        for (int i = 0; i < 4; i++) {
            int id = tid + i * 256;
            int m = id >> 3, c4 = (id & 7) * 4;
            cp_async16(smemA + (uint32_t)(s * AS_STAGE + m * AS_STRIDE + c4) * 4,
                       A + (size_t)(row0 + m) * K + k0 + c4);
        }
        constexpr int BCH = BK * BN / 4;
#pragma unroll
        for (int i = 0; i < BCH / 256; i++) {
            int id = tid + i * 256;
            int k = id / (BN / 4), n4 = (id % (BN / 4)) * 4;
            cp_async16(smemB + (uint32_t)(s * BS_STAGE + k * BS_STRIDE + n4) * 4,
                       W + (size_t)(k0 + k) * Nfull + col0 + n4);
        }
    };

#pragma unroll
    for (int s = 0; s < DEPTH - 1; s++) {
        if (s < KT) load_stage(s, s);
        asm volatile("cp.async.commit_group;" ::: "memory");
    }

    for (int it = 0; it < KT; it++) {
        asm volatile("cp.async.wait_group %0;" :: "n"(DEPTH - 2) : "memory");
        __syncthreads();
        const int nx = it + DEPTH - 1;
        if (nx < KT) load_stage(nx % DEPTH, nx);
        asm volatile("cp.async.commit_group;" ::: "memory");

        const int s = it % DEPTH;
        const float* Asb = As + s * AS_STAGE;
        const float* Bsb = Bs + s * BS_STAGE;
#pragma unroll
        for (int ks = 0; ks < 4; ks++) {
            uint32_t af[2][4];
            uint32_t bf[NF][2];
#pragma unroll
            for (int mf = 0; mf < 2; mf++) {
                int r = warpM * 32 + mf * 16 + g;
                af[mf][0] = __float_as_uint(Asb[r * AS_STRIDE + ks * 8 + q]);
                af[mf][1] = __float_as_uint(Asb[(r + 8) * AS_STRIDE + ks * 8 + q]);
                af[mf][2] = __float_as_uint(Asb[r * AS_STRIDE + ks * 8 + q + 4]);
                af[mf][3] = __float_as_uint(Asb[(r + 8) * AS_STRIDE + ks * 8 + q + 4]);
                if (RA) {
#pragma unroll
                    for (int v = 0; v < 4; v++) af[mf][v] = tf32r_u(af[mf][v]);
                }
            }
#pragma unroll
            for (int nf = 0; nf < NF; nf++) {
                int c = warpN * (BN / 2) + nf * 8 + g;
                bf[nf][0] = __float_as_uint(Bsb[(ks * 8 + q) * BS_STRIDE + c]);
                bf[nf][1] = __float_as_uint(Bsb[(ks * 8 + q + 4) * BS_STRIDE + c]);
            }
#pragma unroll
            for (int mf = 0; mf < 2; mf++)
#pragma unroll
                for (int nf = 0; nf < NF; nf++)
                    mma_tf32(acc[mf][nf], af[mf], bf[nf]);
        }
    }

    // epilogue: bias -> silu -> [gate | +res] -> tf32-rounded store
#pragma unroll
    for (int mf = 0; mf < 2; mf++) {
#pragma unroll
        for (int h = 0; h < 2; h++) {
            const int row = row0 + warpM * 32 + mf * 16 + g + h * 8;
            float4 se0, se1;
            if (GATE) {
                const float4* sp = reinterpret_cast<const float4*>(s8e + (size_t)row * BAS);
                se0 = __ldg(sp); se1 = __ldg(sp + 1);
            }
#pragma unroll
            for (int nf = 0; nf < NF; nf++) {
                const int cl = warpN * (BN / 2) + nf * 8 + 2 * q;   // local col
                const int col = col0 + cl;
                float bv0 = 0.0f, bv1 = 0.0f;
                if (bias) { bv0 = bias[col]; bv1 = bias[col + 1]; }
                float v0 = silu_f(acc[mf][nf][h * 2 + 0] + bv0);
                float v1 = silu_f(acc[mf][nf][h * 2 + 1] + bv1);
                if (GATE) {
                    float g0 = se0.x * gWs[0 * BN + cl] + se0.y * gWs[1 * BN + cl]
                             + se0.z * gWs[2 * BN + cl] + se0.w * gWs[3 * BN + cl]
                             + se1.x * gWs[4 * BN + cl] + se1.y * gWs[5 * BN + cl]
                             + se1.z * gWs[6 * BN + cl] + se1.w * gWs[7 * BN + cl];
                    float g1 = se0.x * gWs[0 * BN + cl + 1] + se0.y * gWs[1 * BN + cl + 1]
                             + se0.z * gWs[2 * BN + cl + 1] + se0.w * gWs[3 * BN + cl + 1]
                             + se1.x * gWs[4 * BN + cl + 1] + se1.y * gWs[5 * BN + cl + 1]
                             + se1.z * gWs[6 * BN + cl + 1] + se1.w * gWs[7 * BN + cl + 1];
                    v0 *= g0; v1 *= g1;
                }
                const size_t off = (size_t)row * Nfull + col;
                if (res) {
                    float2 r = *reinterpret_cast<const float2*>(res + off);
                    v0 += r.x; v1 += r.y;
                }
                uint2 o;
                o.x = tf32r(v0);
                o.y = tf32r(v1);
                *reinterpret_cast<uint2*>(C + off) = o;
            }
        }
    }
}

static constexpr int mma_smem(int BN, int gate) {
    return (3 * (128 * 36 + 32 * (BN + 8)) + (gate ? 8 * BN : 0)) * 4;
}

// ---------------- round all weights, one launch ----------------
struct WSet { const float* src[11]; float* dst[11]; int n4[11]; };
__global__ void round_w_kernel(WSet ws)
{
    int seg = blockIdx.y;
    const float4* s = reinterpret_cast<const float4*>(ws.src[seg]);
    float4* d = reinterpret_cast<float4*>(ws.dst[seg]);
    int n4 = ws.n4[seg];
    for (int i = blockIdx.x * blockDim.x + threadIdx.x; i < n4; i += gridDim.x * blockDim.x) {
        float4 v = s[i];
        uint4 o;
        o.x = tf32r(v.x); o.y = tf32r(v.y); o.z = tf32r(v.z); o.w = tf32r(v.w);
        *reinterpret_cast<uint4*>(&d[i]) = o;
    }
}

// ---------------- s8t = sbf @ W_sbf1 : [T, 8] ----------------
__global__ void s42_kernel(const float* __restrict__ sbf, const float* __restrict__ W1,
                           float* __restrict__ s8out)
{
    __shared__ float w[NSR * BAS];
    for (int i = threadIdx.x; i < NSR * BAS; i += blockDim.x) w[i] = W1[i];
    __syncthreads();
    int t = blockIdx.x * blockDim.x + threadIdx.x;
    const float* srow = sbf + (size_t)t * NSR;
    float o[BAS];
#pragma unroll
    for (int j = 0; j < BAS; j++) o[j] = 0.0f;
#pragma unroll
    for (int i = 0; i < NSR; i++) {
        float r = __ldg(srow + i);
#pragma unroll
        for (int j = 0; j < BAS; j++) o[j] += r * w[i * BAS + j];
    }
    float4 o0 = make_float4(o[0], o[1], o[2], o[3]);
    float4 o1 = make_float4(o[4], o[5], o[6], o[7]);
    reinterpret_cast<float4*>(s8out)[(size_t)t * 2 + 0] = o0;
    reinterpret_cast<float4*>(s8out)[(size_t)t * 2 + 1] = o1;
}

// ---------------- s8e = rbf @ W_rbf1 : [E, 8] ----------------
__global__ void s8e_kernel(const float* __restrict__ rbf, const float* __restrict__ W1,
                           float* __restrict__ s8out)
{
    __shared__ float w[NR * BAS];
    if (threadIdx.x < NR * BAS) w[threadIdx.x] = W1[threadIdx.x];
    __syncthreads();
    int e = blockIdx.x * blockDim.x + threadIdx.x;
    float r[NR];
#pragma unroll
    for (int i = 0; i < NR; i++) r[i] = __ldg(rbf + (size_t)e * NR + i);
    float o[BAS];
#pragma unroll
    for (int j = 0; j < BAS; j++) {
        float s = 0.f;
#pragma unroll
        for (int i = 0; i < NR; i++) s += r[i] * w[i * BAS + j];
        o[j] = s;
    }
    reinterpret_cast<float4*>(s8out)[e * 2 + 0] = make_float4(o[0], o[1], o[2], o[3]);
    reinterpret_cast<float4*>(s8out)[e * 2 + 1] = make_float4(o[4], o[5], o[6], o[7]);
}

// ---------------- zero scratch ----------------
__global__ void zero_kernel(float4* __restrict__ p, int n4)
{
    int i = blockIdx.x * blockDim.x + threadIdx.x;
    int stride = gridDim.x * blockDim.x;
    for (; i < n4; i += stride) p[i] = make_float4(0, 0, 0, 0);
}

// ---------------- triplet pass (v2) ----------------
__global__ void triplet_kernel(const float* __restrict__ s8t,  // [T,8]
                               const int* __restrict__ idx_kj,
                               const int* __restrict__ idx_ji,
                               const float* __restrict__ W2,   // [8,64]
                               const float* __restrict__ xkjd, // [E,64]
                               float* __restrict__ agg)        // [E,64]
{
    __shared__ __align__(16) float sW2[BAS * I_DIM];
    for (int i = threadIdx.x; i < BAS * I_DIM; i += blockDim.x) sW2[i] = W2[i];
    __syncthreads();

    const int lane  = threadIdx.x & 31;
    const int wglob = (blockIdx.x * blockDim.x + threadIdx.x) >> 5;
    const int nwarp = (gridDim.x * blockDim.x) >> 5;
    const int sub = lane >> 4;
    const int sl  = lane & 15;
    const int c   = sl * 4;

    for (int p = wglob; p * 2 < T_TRIP; p += nwarp) {
        int t = p * 2 + sub;
        const float4* s8p = reinterpret_cast<const float4*>(s8t + (size_t)t * BAS);
        float4 slo = __ldg(s8p + 0);
        float4 shi = __ldg(s8p + 1);
        int ekj = __ldg(idx_kj + t);
        int eji = __ldg(idx_ji + t);
        float4 xv = *reinterpret_cast<const float4*>(&xkjd[(size_t)ekj * I_DIM + c]);

        float4 m = make_float4(0, 0, 0, 0);
#pragma unroll
        for (int jj = 0; jj < 4; jj++) {
            float sj = (jj == 0) ? slo.x : (jj == 1) ? slo.y : (jj == 2) ? slo.z : slo.w;
            float4 w = *reinterpret_cast<const float4*>(&sW2[jj * I_DIM + c]);
            m.x += sj * w.x; m.y += sj * w.y; m.z += sj * w.z; m.w += sj * w.w;
        }
#pragma unroll
        for (int jj = 0; jj < 4; jj++) {
            float sj = (jj == 0) ? shi.x : (jj == 1) ? shi.y : (jj == 2) ? shi.z : shi.w;
            float4 w = *reinterpret_cast<const float4*>(&sW2[(jj + 4) * I_DIM + c]);
            m.x += sj * w.x; m.y += sj * w.y; m.z += sj * w.z; m.w += sj * w.w;
        }
        m.x *= xv.x; m.y *= xv.y; m.z *= xv.z; m.w *= xv.w;
        atomicAdd(reinterpret_cast<float4*>(&agg[(size_t)eji * I_DIM + c]), m);
    }
}

// ---------------- launch ----------------
extern "C" void kernel_launch(void* const* d_in, const int* in_sizes, int n_in,
                              void* d_out, int out_size)
{
    const float* x      = (const float*)d_in[0];
    const float* rbf    = (const float*)d_in[1];
    const float* sbf    = (const float*)d_in[2];
    const int*   idx_kj = (const int*)d_in[3];
    const int*   idx_ji = (const int*)d_in[4];
    const float* W_ji   = (const float*)d_in[5];
    const float* b_ji   = (const float*)d_in[6];
    const float* W_kj   = (const float*)d_in[7];
    const float* b_kj   = (const float*)d_in[8];
    const float* W_rbf1 = (const float*)d_in[9];
    const float* W_rbf2 = (const float*)d_in[10];
    const float* W_sbf1 = (const float*)d_in[11];
    const float* W_sbf2 = (const float*)d_in[12];
    const float* W_down = (const float*)d_in[13];
    const float* W_up   = (const float*)d_in[14];
    const float* Wb1_1  = (const float*)d_in[15];
    const float* bb1_1  = (const float*)d_in[16];
    const float* Wb1_2  = (const float*)d_in[17];
    const float* bb1_2  = (const float*)d_in[18];
    const float* W_lin  = (const float*)d_in[19];
    const float* b_lin  = (const float*)d_in[20];
    const float* Wa1_1  = (const float*)d_in[21];
    const float* ba1_1  = (const float*)d_in[22];
    const float* Wa1_2  = (const float*)d_in[23];
    const float* ba1_2  = (const float*)d_in[24];
    const float* Wa2_1  = (const float*)d_in[25];
    const float* ba2_1  = (const float*)d_in[26];
    const float* Wa2_2  = (const float*)d_in[27];
    const float* ba2_2  = (const float*)d_in[28];
    float* out = (float*)d_out;

    float *xji, *bufA, *bufB, *xkjd, *agg, *s8t, *s8e, *wr;
    cudaGetSymbolAddress((void**)&xji,  g_xji);
    cudaGetSymbolAddress((void**)&bufA, g_bufA);
    cudaGetSymbolAddress((void**)&bufB, g_bufB);
    cudaGetSymbolAddress((void**)&xkjd, g_xkjd);
    cudaGetSymbolAddress((void**)&agg,  g_agg);
    cudaGetSymbolAddress((void**)&s8t,  g_s8t);
    cudaGetSymbolAddress((void**)&s8e,  g_s8e);
    cudaGetSymbolAddress((void**)&wr,   g_wr);

    constexpr int SM_BIG   = mma_smem(128, 0);   // 107,520 B
    constexpr int SM_GATE  = mma_smem(128, 1);   // 111,616 B (still occ 2)
    constexpr int SM_DOWN  = mma_smem(64, 0);
    cudaFuncSetAttribute(mma_gemm<128, 256, 0, 0>, cudaFuncAttributeMaxDynamicSharedMemorySize, SM_BIG);
    cudaFuncSetAttribute(mma_gemm<128, 256, 0, 1>, cudaFuncAttributeMaxDynamicSharedMemorySize, SM_BIG);
    cudaFuncSetAttribute(mma_gemm<128, 256, 1, 1>, cudaFuncAttributeMaxDynamicSharedMemorySize, SM_GATE);
    cudaFuncSetAttribute(mma_gemm<64, 256, 0, 0>,  cudaFuncAttributeMaxDynamicSharedMemorySize, SM_DOWN);
    cudaFuncSetAttribute(mma_gemm<128, 64, 0, 0>,  cudaFuncAttributeMaxDynamicSharedMemorySize, SM_BIG);

    const dim3 gBig(2, E_EDGES / 128);
    const dim3 gDown(1, E_EDGES / 128);

    // 0: round all weights (single launch)
    WSet ws;
    const float* srcs[11] = {W_ji, W_kj, Wb1_1, Wb1_2, W_lin, Wa1_1, Wa1_2, Wa2_1, Wa2_2, W_down, W_up};
    const int offs[11]    = {WO_JI, WO_KJ, WO_B11, WO_B12, WO_LIN, WO_A11, WO_A12, WO_A21, WO_A22, WO_DOWN, WO_UP};
    const int n4s[11]     = {16384, 16384, 16384, 16384, 16384, 16384, 16384, 16384, 16384, 4096, 4096};
    for (int i = 0; i < 11; i++) { ws.src[i] = srcs[i]; ws.dst[i] = wr + offs[i]; ws.n4[i] = n4s[i]; }
    round_w_kernel<<<dim3(16, 11), 256>>>(ws);

    // 1: s8e = rbf @ W_rbf1  (edge gate basis)
    s8e_kernel<<<E_EDGES / 256, 256>>>(rbf, W_rbf1, s8e);
    // 2: s8t = sbf @ W_sbf1  (triplet basis)
    s42_kernel<<<T_TRIP / 256, 256>>>(sbf, W_sbf1, s8t);
    // 3: x_kj_gated = silu(x@W_kj + b) * (s8e@W_rbf2)   [GATE+RA fused, reads raw x]
    mma_gemm<128, 256, 1, 1><<<gBig, 256, SM_GATE>>>(x, wr + WO_KJ, b_kj, nullptr, bufA, H_DIM, s8e, W_rbf2);
    // 4: x_kj_down = silu(x_kj_gated @ W_down)
    mma_gemm<64, 256, 0, 0><<<gDown, 256, SM_DOWN>>>(bufA, wr + WO_DOWN, nullptr, nullptr, xkjd, I_DIM, nullptr, nullptr);
    // 5: zero agg
    zero_kernel<<<1024, 256>>>((float4*)agg, E_EDGES * I_DIM / 4);
    // 6: triplet message passing
    triplet_kernel<<<2048, 256>>>(s8t, idx_kj, idx_ji, W_sbf2, xkjd, agg);
    // 7: x_ji = silu(x@W_ji + b)   [RA, reads raw x]
    mma_gemm<128, 256, 0, 1><<<gBig, 256, SM_BIG>>>(x, wr + WO_JI, b_ji, nullptr, xji, H_DIM, nullptr, nullptr);
    // 8: h = x_ji + silu(agg @ W_up)
    mma_gemm<128, 64, 0, 0><<<gBig, 256, SM_BIG>>>(agg, wr + WO_UP, nullptr, xji, bufA, H_DIM, nullptr, nullptr);
    // 9-10: pre-skip residual pair
    mma_gemm<128, 256, 0, 0><<<gBig, 256, SM_BIG>>>(bufA, wr + WO_B11, bb1_1, nullptr, bufB, H_DIM, nullptr, nullptr);
    mma_gemm<128, 256, 0, 0><<<gBig, 256, SM_BIG>>>(bufB, wr + WO_B12, bb1_2, bufA, bufA, H_DIM, nullptr, nullptr);
    // 11: skip: h = silu(h@W_lin+b) + x
    mma_gemm<128, 256, 0, 0><<<gBig, 256, SM_BIG>>>(bufA, wr + WO_LIN, b_lin, x, bufB, H_DIM, nullptr, nullptr);
    // 12-13: post-skip residual pair 1
    mma_gemm<128, 256, 0, 0><<<gBig, 256, SM_BIG>>>(bufB, wr + WO_A11, ba1_1, nullptr, bufA, H_DIM, nullptr, nullptr);
    mma_gemm<128, 256, 0, 0><<<gBig, 256, SM_BIG>>>(bufA, wr + WO_A12, ba1_2, bufB, bufB, H_DIM, nullptr, nullptr);
    // 14-15: post-skip residual pair 2 -> final output
    mma_gemm<128, 256, 0, 0><<<gBig, 256, SM_BIG>>>(bufB, wr + WO_A21, ba2_1, nullptr, bufA, H_DIM, nullptr, nullptr);
    mma_gemm<128, 256, 0, 0><<<gBig, 256, SM_BIG>>>(bufA, wr + WO_A22, ba2_2, bufB, out, H_DIM, nullptr, nullptr);
}

// round 13
// speedup vs baseline: 1.4290x; 1.0187x over previous
#include <cuda_runtime.h>
#include <cstdint>
#include <cstddef>

// ---------------- problem constants ----------------
static constexpr int E_EDGES = 131072;
static constexpr int T_TRIP  = 1048576;
static constexpr int H_DIM   = 256;
static constexpr int I_DIM   = 64;
static constexpr int NR      = 6;
static constexpr int NSR     = 42;
static constexpr int BAS     = 8;

// ---------------- scratch (static device memory) ----------------
__device__ float g_xji [(size_t)E_EDGES * H_DIM];
__device__ float g_bufA[(size_t)E_EDGES * H_DIM];
__device__ float g_bufB[(size_t)E_EDGES * H_DIM];
__device__ float g_xkjd[(size_t)E_EDGES * I_DIM];
__device__ float g_agg [(size_t)E_EDGES * I_DIM];
__device__ float g_s8t [(size_t)T_TRIP * BAS];      // sbf @ W_sbf1  [T,8]
__device__ float g_s8e [(size_t)E_EDGES * BAS];     // rbf @ W_rbf1  [E,8]
__device__ float g_wr  [622592];   // tf32-rounded weights, concatenated

// weight offsets inside g_wr
static constexpr int WO_JI   = 0;
static constexpr int WO_KJ   = 65536;
static constexpr int WO_B11  = 131072;
static constexpr int WO_B12  = 196608;
static constexpr int WO_LIN  = 262144;
static constexpr int WO_A11  = 327680;
static constexpr int WO_A12  = 393216;
static constexpr int WO_A21  = 458752;
static constexpr int WO_A22  = 524288;
static constexpr int WO_DOWN = 589824;   // 256*64
static constexpr int WO_UP   = 606208;   // 64*256

// ---------------- helpers ----------------
__device__ __forceinline__ uint32_t smem_to_u32(const void* p) {
    uint32_t a;
    asm("{ .reg .u64 t; cvta.to.shared.u64 t, %1; cvt.u32.u64 %0, t; }" : "=r"(a) : "l"(p));
    return a;
}
__device__ __forceinline__ uint32_t tf32r(float v) {
    uint32_t o; asm("cvt.rna.tf32.f32 %0, %1;" : "=r"(o) : "f"(v)); return o;
}
__device__ __forceinline__ float silu_f(float v) {
    return v * (1.0f / (1.0f + __expf(-v)));
}
__device__ __forceinline__ void cp_async16(uint32_t dst, const void* src) {
    asm volatile("cp.async.cg.shared.global [%0], [%1], 16;" :: "r"(dst), "l"(src));
}
__device__ __forceinline__ void mma_tf32(float d[4], const uint32_t a[4], const uint32_t b[2]) {
    asm volatile(
        "mma.sync.aligned.m16n8k8.row.col.f32.tf32.tf32.f32 "
        "{%0,%1,%2,%3}, {%4,%5,%6,%7}, {%8,%9}, {%0,%1,%2,%3};"
        : "+f"(d[0]), "+f"(d[1]), "+f"(d[2]), "+f"(d[3])
        : "r"(a[0]), "r"(a[1]), "r"(a[2]), "r"(a[3]), "r"(b[0]), "r"(b[1]));
}

// shared GEMM core config
static constexpr int BM_ = 128, BK_ = 32, DEPTH_ = 3;
static constexpr int AS_STRIDE_ = BK_ + 4;            // 36
static constexpr int AS_STAGE_  = BM_ * AS_STRIDE_;

// ============ mma.sync tf32 GEMM (R9 core, optional gate epilogue) ============
template <int BN, int K, int GATE>
__global__ void __launch_bounds__(256, 2)
mma_gemm(const float* __restrict__ A, const float* __restrict__ W,
         const float* __restrict__ bias, const float* __restrict__ res,
         float* __restrict__ C, int Nfull,
         const float* __restrict__ s8e, const float* __restrict__ Wg)
{
    constexpr int KT = K / BK_;
    constexpr int BS_STRIDE = BN + 8;
    constexpr int BS_STAGE  = BK_ * BS_STRIDE;
    constexpr int NF = BN / 16;

    extern __shared__ float smf[];
    float* As = smf;
    float* Bs = smf + DEPTH_ * AS_STAGE_;
    float* gWs = Bs + DEPTH_ * BS_STAGE;
    const uint32_t smemA = smem_to_u32(As);
    const uint32_t smemB = smem_to_u32(Bs);

    const int tid = threadIdx.x, lane = tid & 31, wid = tid >> 5;
    const int warpM = wid >> 1, warpN = wid & 1;
    const int row0 = blockIdx.y * BM_;
    const int col0 = blockIdx.x * BN;
    const int g = lane >> 2, q = lane & 3;

    if (GATE) {
        for (int i = tid; i < BAS * BN; i += 256) {
            int j = i / BN, n = i % BN;
            gWs[j * BN + n] = Wg[j * Nfull + col0 + n];
        }
    }

    float acc[2][NF][4];
#pragma unroll
    for (int mf = 0; mf < 2; mf++)
#pragma unroll
        for (int nf = 0; nf < NF; nf++)
#pragma unroll
            for (int v = 0; v < 4; v++) acc[mf][nf][v] = 0.0f;

    auto load_stage = [&](int s, int kt) {
        const int k0 = kt * BK_;
#pragma unroll
        for (int i = 0; i < 4; i++) {
            int id = tid + i * 256;
            int m = id >> 3, c4 = (id & 7) * 4;
            cp_async16(smemA + (uint32_t)(s * AS_STAGE_ + m * AS_STRIDE_ + c4) * 4,
                       A + (size_t)(row0 + m) * K + k0 + c4);
        }
        constexpr int BCH = BK_ * BN / 4;
#pragma unroll
        for (int i = 0; i < BCH / 256; i++) {
            int id = tid + i * 256;
            int k = id / (BN / 4), n4 = (id % (BN / 4)) * 4;
            cp_async16(smemB + (uint32_t)(s * BS_STAGE + k * BS_STRIDE + n4) * 4,
                       W + (size_t)(k0 + k) * Nfull + col0 + n4);
        }
    };

#pragma unroll
    for (int s = 0; s < DEPTH_ - 1; s++) {
        if (s < KT) load_stage(s, s);
        asm volatile("cp.async.commit_group;" ::: "memory");
    }

    for (int it = 0; it < KT; it++) {
        asm volatile("cp.async.wait_group %0;" :: "n"(DEPTH_ - 2) : "memory");
        __syncthreads();
        const int nx = it + DEPTH_ - 1;
        if (nx < KT) load_stage(nx % DEPTH_, nx);
        asm volatile("cp.async.commit_group;" ::: "memory");

        const int s = it % DEPTH_;
        const float* Asb = As + s * AS_STAGE_;
        const float* Bsb = Bs + s * BS_STAGE;
#pragma unroll
        for (int ks = 0; ks < 4; ks++) {
            uint32_t af[2][4];
            uint32_t bf[NF][2];
#pragma unroll
            for (int mf = 0; mf < 2; mf++) {
                int r = warpM * 32 + mf * 16 + g;
                af[mf][0] = __float_as_uint(Asb[r * AS_STRIDE_ + ks * 8 + q]);
                af[mf][1] = __float_as_uint(Asb[(r + 8) * AS_STRIDE_ + ks * 8 + q]);
                af[mf][2] = __float_as_uint(Asb[r * AS_STRIDE_ + ks * 8 + q + 4]);
                af[mf][3] = __float_as_uint(Asb[(r + 8) * AS_STRIDE_ + ks * 8 + q + 4]);
            }
#pragma unroll
            for (int nf = 0; nf < NF; nf++) {
                int c = warpN * (BN / 2) + nf * 8 + g;
                bf[nf][0] = __float_as_uint(Bsb[(ks * 8 + q) * BS_STRIDE + c]);
                bf[nf][1] = __float_as_uint(Bsb[(ks * 8 + q + 4) * BS_STRIDE + c]);
            }
#pragma unroll
            for (int mf = 0; mf < 2; mf++)
#pragma unroll
                for (int nf = 0; nf < NF; nf++)
                    mma_tf32(acc[mf][nf], af[mf], bf[nf]);
        }
    }

#pragma unroll
    for (int mf = 0; mf < 2; mf++) {
#pragma unroll
        for (int h = 0; h < 2; h++) {
            const int row = row0 + warpM * 32 + mf * 16 + g + h * 8;
            float4 se0, se1;
            if (GATE) {
                const float4* sp = reinterpret_cast<const float4*>(s8e + (size_t)row * BAS);
                se0 = __ldg(sp); se1 = __ldg(sp + 1);
            }
#pragma unroll
            for (int nf = 0; nf < NF; nf++) {
                const int cl = warpN * (BN / 2) + nf * 8 + 2 * q;
                const int col = col0 + cl;
                float bv0 = 0.0f, bv1 = 0.0f;
                if (bias) { bv0 = bias[col]; bv1 = bias[col + 1]; }
                float v0 = silu_f(acc[mf][nf][h * 2 + 0] + bv0);
                float v1 = silu_f(acc[mf][nf][h * 2 + 1] + bv1);
                if (GATE) {
                    float g0 = se0.x * gWs[0 * BN + cl] + se0.y * gWs[1 * BN + cl]
                             + se0.z * gWs[2 * BN + cl] + se0.w * gWs[3 * BN + cl]
                             + se1.x * gWs[4 * BN + cl] + se1.y * gWs[5 * BN + cl]
                             + se1.z * gWs[6 * BN + cl] + se1.w * gWs[7 * BN + cl];
                    float g1 = se0.x * gWs[0 * BN + cl + 1] + se0.y * gWs[1 * BN + cl + 1]
                             + se0.z * gWs[2 * BN + cl + 1] + se0.w * gWs[3 * BN + cl + 1]
                             + se1.x * gWs[4 * BN + cl + 1] + se1.y * gWs[5 * BN + cl + 1]
                             + se1.z * gWs[6 * BN + cl + 1] + se1.w * gWs[7 * BN + cl + 1];
                    v0 *= g0; v1 *= g1;
                }
                const size_t off = (size_t)row * Nfull + col;
                if (res) {
                    float2 r = *reinterpret_cast<const float2*>(res + off);
                    v0 += r.x; v1 += r.y;
                }
                uint2 o;
                o.x = tf32r(v0);
                o.y = tf32r(v1);
                *reinterpret_cast<uint2*>(C + off) = o;
            }
        }
    }
}

// ============ dual GEMM: kj (gated) + ji in one launch, shared A=x ============
// grid (4, E/128): bx<2 -> kj half (gate), bx>=2 -> ji half. col0 = (bx&1)*128.
__global__ void __launch_bounds__(256, 2)
dual_gemm(const float* __restrict__ A,
          const float* __restrict__ Wkj, const float* __restrict__ bkj,
          const float* __restrict__ Wji, const float* __restrict__ bji,
          float* __restrict__ Ckj, float* __restrict__ Cji,
          const float* __restrict__ s8e, const float* __restrict__ Wg)
{
    constexpr int BN = 128, K = 256, KT = K / BK_;
    constexpr int BS_STRIDE = BN + 8;
    constexpr int BS_STAGE  = BK_ * BS_STRIDE;
    constexpr int NF = BN / 16;

    extern __shared__ float smf[];
    float* As = smf;
    float* Bs = smf + DEPTH_ * AS_STAGE_;
    float* gWs = Bs + DEPTH_ * BS_STAGE;
    const uint32_t smemA = smem_to_u32(As);
    const uint32_t smemB = smem_to_u32(Bs);

    const int tid = threadIdx.x, lane = tid & 31, wid = tid >> 5;
    const int warpM = wid >> 1, warpN = wid & 1;
    const int row0 = blockIdx.y * BM_;
    const int is_ji = blockIdx.x >> 1;
    const int col0 = (blockIdx.x & 1) * BN;
    const int g = lane >> 2, q = lane & 3;

    const float* W    = is_ji ? Wji : Wkj;
    const float* bias = is_ji ? bji : bkj;
    float* C          = is_ji ? Cji : Ckj;

    if (!is_ji) {
        for (int i = tid; i < BAS * BN; i += 256) {
            int j = i / BN, n = i % BN;
            gWs[j * BN + n] = Wg[j * H_DIM + col0 + n];
        }
    }

    float acc[2][NF][4];
#pragma unroll
    for (int mf = 0; mf < 2; mf++)
#pragma unroll
        for (int nf = 0; nf < NF; nf++)
#pragma unroll
            for (int v = 0; v < 4; v++) acc[mf][nf][v] = 0.0f;

    auto load_stage = [&](int s, int kt) {
        const int k0 = kt * BK_;
#pragma unroll
        for (int i = 0; i < 4; i++) {
            int id = tid + i * 256;
            int m = id >> 3, c4 = (id & 7) * 4;
            cp_async16(smemA + (uint32_t)(s * AS_STAGE_ + m * AS_STRIDE_ + c4) * 4,
                       A + (size_t)(row0 + m) * K + k0 + c4);
        }
        constexpr int BCH = BK_ * BN / 4;
#pragma unroll
        for (int i = 0; i < BCH / 256; i++) {
            int id = tid + i * 256;
            int k = id / (BN / 4), n4 = (id % (BN / 4)) * 4;
            cp_async16(smemB + (uint32_t)(s * BS_STAGE + k * BS_STRIDE + n4) * 4,
                       W + (size_t)(k0 + k) * H_DIM + col0 + n4);
        }
    };

#pragma unroll
    for (int s = 0; s < DEPTH_ - 1; s++) {
        load_stage(s, s);
        asm volatile("cp.async.commit_group;" ::: "memory");
    }

    for (int it = 0; it < KT; it++) {
        asm volatile("cp.async.wait_group %0;" :: "n"(DEPTH_ - 2) : "memory");
        __syncthreads();
        const int nx = it + DEPTH_ - 1;
        if (nx < KT) load_stage(nx % DEPTH_, nx);
        asm volatile("cp.async.commit_group;" ::: "memory");

        const int s = it % DEPTH_;
        const float* Asb = As + s * AS_STAGE_;
        const float* Bsb = Bs + s * BS_STAGE;
#pragma unroll
        for (int ks = 0; ks < 4; ks++) {
            uint32_t af[2][4];
            uint32_t bf[NF][2];
#pragma unroll
            for (int mf = 0; mf < 2; mf++) {
                int r = warpM * 32 + mf * 16 + g;
                af[mf][0] = __float_as_uint(Asb[r * AS_STRIDE_ + ks * 8 + q]);
                af[mf][1] = __float_as_uint(Asb[(r + 8) * AS_STRIDE_ + ks * 8 + q]);
                af[mf][2] = __float_as_uint(Asb[r * AS_STRIDE_ + ks * 8 + q + 4]);
                af[mf][3] = __float_as_uint(Asb[(r + 8) * AS_STRIDE_ + ks * 8 + q + 4]);
            }
#pragma unroll
            for (int nf = 0; nf < NF; nf++) {
                int c = warpN * (BN / 2) + nf * 8 + g;
                bf[nf][0] = __float_as_uint(Bsb[(ks * 8 + q) * BS_STRIDE + c]);
                bf[nf][1] = __float_as_uint(Bsb[(ks * 8 + q + 4) * BS_STRIDE + c]);
            }
#pragma unroll
            for (int mf = 0; mf < 2; mf++)
#pragma unroll
                for (int nf = 0; nf < NF; nf++)
                    mma_tf32(acc[mf][nf], af[mf], bf[nf]);
        }
    }

#pragma unroll
    for (int mf = 0; mf < 2; mf++) {
#pragma unroll
        for (int h = 0; h < 2; h++) {
            const int row = row0 + warpM * 32 + mf * 16 + g + h * 8;
            float4 se0 = make_float4(0, 0, 0, 0), se1 = make_float4(0, 0, 0, 0);
            if (!is_ji) {
                const float4* sp = reinterpret_cast<const float4*>(s8e + (size_t)row * BAS);
                se0 = __ldg(sp); se1 = __ldg(sp + 1);
            }
#pragma unroll
            for (int nf = 0; nf < NF; nf++) {
                const int cl = warpN * (BN / 2) + nf * 8 + 2 * q;
                const int col = col0 + cl;
                float v0 = silu_f(acc[mf][nf][h * 2 + 0] + bias[col]);
                float v1 = silu_f(acc[mf][nf][h * 2 + 1] + bias[col + 1]);
                if (!is_ji) {
                    float g0 = se0.x * gWs[0 * BN + cl] + se0.y * gWs[1 * BN + cl]
                             + se0.z * gWs[2 * BN + cl] + se0.w * gWs[3 * BN + cl]
                             + se1.x * gWs[4 * BN + cl] + se1.y * gWs[5 * BN + cl]
                             + se1.z * gWs[6 * BN + cl] + se1.w * gWs[7 * BN + cl];
                    float g1 = se0.x * gWs[0 * BN + cl + 1] + se0.y * gWs[1 * BN + cl + 1]
                             + se0.z * gWs[2 * BN + cl + 1] + se0.w * gWs[3 * BN + cl + 1]
                             + se1.x * gWs[4 * BN + cl + 1] + se1.y * gWs[5 * BN + cl + 1]
                             + se1.z * gWs[6 * BN + cl + 1] + se1.w * gWs[7 * BN + cl + 1];
                    v0 *= g0; v1 *= g1;
                }
                const size_t off = (size_t)row * H_DIM + col;
                uint2 o;
                o.x = tf32r(v0);
                o.y = tf32r(v1);
                *reinterpret_cast<uint2*>(C + off) = o;
            }
        }
    }
}

static constexpr int mma_smem(int BN, int gate) {
    return (3 * (128 * 36 + 32 * (BN + 8)) + (gate ? 8 * BN : 0)) * 4;
}

// ---------------- round all weights, one launch ----------------
struct WSet { const float* src[11]; float* dst[11]; int n4[11]; };
__global__ void round_w_kernel(WSet ws)
{
    int seg = blockIdx.y;
    const float4* s = reinterpret_cast<const float4*>(ws.src[seg]);
    float4* d = reinterpret_cast<float4*>(ws.dst[seg]);
    int n4 = ws.n4[seg];
    for (int i = blockIdx.x * blockDim.x + threadIdx.x; i < n4; i += gridDim.x * blockDim.x) {
        float4 v = s[i];
        uint4 o;
        o.x = tf32r(v.x); o.y = tf32r(v.y); o.z = tf32r(v.z); o.w = tf32r(v.w);
        *reinterpret_cast<uint4*>(&d[i]) = o;
    }
}

// ---------------- s8t = sbf @ W_sbf1 : [T, 8] ----------------
__global__ void s42_kernel(const float* __restrict__ sbf, const float* __restrict__ W1,
                           float* __restrict__ s8out)
{
    __shared__ float w[NSR * BAS];
    for (int i = threadIdx.x; i < NSR * BAS; i += blockDim.x) w[i] = W1[i];
    __syncthreads();
    int t = blockIdx.x * blockDim.x + threadIdx.x;
    const float* srow = sbf + (size_t)t * NSR;
    float o[BAS];
#pragma unroll
    for (int j = 0; j < BAS; j++) o[j] = 0.0f;
#pragma unroll
    for (int i = 0; i < NSR; i++) {
        float r = __ldg(srow + i);
#pragma unroll
        for (int j = 0; j < BAS; j++) o[j] += r * w[i * BAS + j];
    }
    reinterpret_cast<float4*>(s8out)[(size_t)t * 2 + 0] = make_float4(o[0], o[1], o[2], o[3]);
    reinterpret_cast<float4*>(s8out)[(size_t)t * 2 + 1] = make_float4(o[4], o[5], o[6], o[7]);
}

// ---------------- s8e = rbf @ W_rbf1 : [E, 8] ----------------
__global__ void s8e_kernel(const float* __restrict__ rbf, const float* __restrict__ W1,
                           float* __restrict__ s8out)
{
    __shared__ float w[NR * BAS];
    if (threadIdx.x < NR * BAS) w[threadIdx.x] = W1[threadIdx.x];
    __syncthreads();
    int e = blockIdx.x * blockDim.x + threadIdx.x;
    float r[NR];
#pragma unroll
    for (int i = 0; i < NR; i++) r[i] = __ldg(rbf + (size_t)e * NR + i);
    float o[BAS];
#pragma unroll
    for (int j = 0; j < BAS; j++) {
        float s = 0.f;
#pragma unroll
        for (int i = 0; i < NR; i++) s += r[i] * w[i * BAS + j];
        o[j] = s;
    }
    reinterpret_cast<float4*>(s8out)[e * 2 + 0] = make_float4(o[0], o[1], o[2], o[3]);
    reinterpret_cast<float4*>(s8out)[e * 2 + 1] = make_float4(o[4], o[5], o[6], o[7]);
}

// ---------------- zero scratch ----------------
__global__ void zero_kernel(float4* __restrict__ p, int n4)
{
    int i = blockIdx.x * blockDim.x + threadIdx.x;
    int stride = gridDim.x * blockDim.x;
    for (; i < n4; i += stride) p[i] = make_float4(0, 0, 0, 0);
}

// ---------------- triplet pass ----------------
__global__ void triplet_kernel(const float* __restrict__ s8t,
                               const int* __restrict__ idx_kj,
                               const int* __restrict__ idx_ji,
                               const float* __restrict__ W2,
                               const float* __restrict__ xkjd,
                               float* __restrict__ agg)
{
    __shared__ __align__(16) float sW2[BAS * I_DIM];
    for (int i = threadIdx.x; i < BAS * I_DIM; i += blockDim.x) sW2[i] = W2[i];
    __syncthreads();

    const int lane  = threadIdx.x & 31;
    const int wglob = (blockIdx.x * blockDim.x + threadIdx.x) >> 5;
    const int nwarp = (gridDim.x * blockDim.x) >> 5;
    const int sub = lane >> 4;
    const int sl  = lane & 15;
    const int c   = sl * 4;

    for (int p = wglob; p * 2 < T_TRIP; p += nwarp) {
        int t = p * 2 + sub;
        const float4* s8p = reinterpret_cast<const float4*>(s8t + (size_t)t * BAS);
        float4 slo = __ldg(s8p + 0);
        float4 shi = __ldg(s8p + 1);
        int ekj = __ldg(idx_kj + t);
        int eji = __ldg(idx_ji + t);
        float4 xv = *reinterpret_cast<const float4*>(&xkjd[(size_t)ekj * I_DIM + c]);

        float4 m = make_float4(0, 0, 0, 0);
#pragma unroll
        for (int jj = 0; jj < 4; jj++) {
            float sj = (jj == 0) ? slo.x : (jj == 1) ? slo.y : (jj == 2) ? slo.z : slo.w;
            float4 w = *reinterpret_cast<const float4*>(&sW2[jj * I_DIM + c]);
            m.x += sj * w.x; m.y += sj * w.y; m.z += sj * w.z; m.w += sj * w.w;
        }
#pragma unroll
        for (int jj = 0; jj < 4; jj++) {
            float sj = (jj == 0) ? shi.x : (jj == 1) ? shi.y : (jj == 2) ? shi.z : shi.w;
            float4 w = *reinterpret_cast<const float4*>(&sW2[(jj + 4) * I_DIM + c]);
            m.x += sj * w.x; m.y += sj * w.y; m.z += sj * w.z; m.w += sj * w.w;
        }
        m.x *= xv.x; m.y *= xv.y; m.z *= xv.z; m.w *= xv.w;
        atomicAdd(reinterpret_cast<float4*>(&agg[(size_t)eji * I_DIM + c]), m);
    }
}

// ---------------- launch ----------------
extern "C" void kernel_launch(void* const* d_in, const int* in_sizes, int n_in,
                              void* d_out, int out_size)
{
    const float* x      = (const float*)d_in[0];
    const float* rbf    = (const float*)d_in[1];
    const float* sbf    = (const float*)d_in[2];
    const int*   idx_kj = (const int*)d_in[3];
    const int*   idx_ji = (const int*)d_in[4];
    const float* W_ji   = (const float*)d_in[5];
    const float* b_ji   = (const float*)d_in[6];
    const float* W_kj   = (const float*)d_in[7];
    const float* b_kj   = (const float*)d_in[8];
    const float* W_rbf1 = (const float*)d_in[9];
    const float* W_rbf2 = (const float*)d_in[10];
    const float* W_sbf1 = (const float*)d_in[11];
    const float* W_sbf2 = (const float*)d_in[12];
    const float* W_down = (const float*)d_in[13];
    const float* W_up   = (const float*)d_in[14];
    const float* Wb1_1  = (const float*)d_in[15];
    const float* bb1_1  = (const float*)d_in[16];
    const float* Wb1_2  = (const float*)d_in[17];
    const float* bb1_2  = (const float*)d_in[18];
    const float* W_lin  = (const float*)d_in[19];
    const float* b_lin  = (const float*)d_in[20];
    const float* Wa1_1  = (const float*)d_in[21];
    const float* ba1_1  = (const float*)d_in[22];
    const float* Wa1_2  = (const float*)d_in[23];
    const float* ba1_2  = (const float*)d_in[24];
    const float* Wa2_1  = (const float*)d_in[25];
    const float* ba2_1  = (const float*)d_in[26];
    const float* Wa2_2  = (const float*)d_in[27];
    const float* ba2_2  = (const float*)d_in[28];
    float* out = (float*)d_out;

    float *xji, *bufA, *bufB, *xkjd, *agg, *s8t, *s8e, *wr;
    cudaGetSymbolAddress((void**)&xji,  g_xji);
    cudaGetSymbolAddress((void**)&bufA, g_bufA);
    cudaGetSymbolAddress((void**)&bufB, g_bufB);
    cudaGetSymbolAddress((void**)&xkjd, g_xkjd);
    cudaGetSymbolAddress((void**)&agg,  g_agg);
    cudaGetSymbolAddress((void**)&s8t,  g_s8t);
    cudaGetSymbolAddress((void**)&s8e,  g_s8e);
    cudaGetSymbolAddress((void**)&wr,   g_wr);

    constexpr int SM_BIG   = mma_smem(128, 0);
    constexpr int SM_GATE  = mma_smem(128, 1);
    constexpr int SM_DOWN  = mma_smem(64, 0);
    cudaFuncSetAttribute(mma_gemm<128, 256, 0>, cudaFuncAttributeMaxDynamicSharedMemorySize, SM_BIG);
    cudaFuncSetAttribute(mma_gemm<64, 256, 0>,  cudaFuncAttributeMaxDynamicSharedMemorySize, SM_DOWN);
    cudaFuncSetAttribute(mma_gemm<128, 64, 0>,  cudaFuncAttributeMaxDynamicSharedMemorySize, SM_BIG);
    cudaFuncSetAttribute(dual_gemm,             cudaFuncAttributeMaxDynamicSharedMemorySize, SM_GATE);

    const dim3 gBig(2, E_EDGES / 128);
    const dim3 gDown(1, E_EDGES / 128);
    const dim3 gDual(4, E_EDGES / 128);

    // 0: round all weights
    WSet ws;
    const float* srcs[11] = {W_ji, W_kj, Wb1_1, Wb1_2, W_lin, Wa1_1, Wa1_2, Wa2_1, Wa2_2, W_down, W_up};
    const int offs[11]    = {WO_JI, WO_KJ, WO_B11, WO_B12, WO_LIN, WO_A11, WO_A12, WO_A21, WO_A22, WO_DOWN, WO_UP};
    const int n4s[11]     = {16384, 16384, 16384, 16384, 16384, 16384, 16384, 16384, 16384, 4096, 4096};
    for (int i = 0; i < 11; i++) { ws.src[i] = srcs[i]; ws.dst[i] = wr + offs[i]; ws.n4[i] = n4s[i]; }
    round_w_kernel<<<dim3(16, 11), 256>>>(ws);

    // 1: s8e = rbf @ W_rbf1
    s8e_kernel<<<E_EDGES / 256, 256>>>(rbf, W_rbf1, s8e);
    // 2: s8t = sbf @ W_sbf1
    s42_kernel<<<T_TRIP / 256, 256>>>(sbf, W_sbf1, s8t);
    // 3: dual: x_kj_gated -> bufA (gate fused), x_ji -> xji   (A = raw x, shared in L2)
    dual_gemm<<<gDual, 256, SM_GATE>>>(x, wr + WO_KJ, b_kj, wr + WO_JI, b_ji,
                                       bufA, xji, s8e, W_rbf2);
    // 4: x_kj_down = silu(x_kj_gated @ W_down)
    mma_gemm<64, 256, 0><<<gDown, 256, SM_DOWN>>>(bufA, wr + WO_DOWN, nullptr, nullptr, xkjd, I_DIM, nullptr, nullptr);
    // 5: zero agg
    zero_kernel<<<1024, 256>>>((float4*)agg, E_EDGES * I_DIM / 4);
    // 6: triplet message passing
    triplet_kernel<<<2048, 256>>>(s8t, idx_kj, idx_ji, W_sbf2, xkjd, agg);
    // 7: h = x_ji + silu(agg @ W_up)
    mma_gemm<128, 64, 0><<<gBig, 256, SM_BIG>>>(agg, wr + WO_UP, nullptr, xji, bufA, H_DIM, nullptr, nullptr);
    // 8-9: pre-skip residual pair
    mma_gemm<128, 256, 0><<<gBig, 256, SM_BIG>>>(bufA, wr + WO_B11, bb1_1, nullptr, bufB, H_DIM, nullptr, nullptr);
    mma_gemm<128, 256, 0><<<gBig, 256, SM_BIG>>>(bufB, wr + WO_B12, bb1_2, bufA, bufA, H_DIM, nullptr, nullptr);
    // 10: skip: h = silu(h@W_lin+b) + x
    mma_gemm<128, 256, 0><<<gBig, 256, SM_BIG>>>(bufA, wr + WO_LIN, b_lin, x, bufB, H_DIM, nullptr, nullptr);
    // 11-12: post-skip residual pair 1
    mma_gemm<128, 256, 0><<<gBig, 256, SM_BIG>>>(bufB, wr + WO_A11, ba1_1, nullptr, bufA, H_DIM, nullptr, nullptr);
    mma_gemm<128, 256, 0><<<gBig, 256, SM_BIG>>>(bufA, wr + WO_A12, ba1_2, bufB, bufB, H_DIM, nullptr, nullptr);
    // 13-14: post-skip residual pair 2 -> final output
    mma_gemm<128, 256, 0><<<gBig, 256, SM_BIG>>>(bufB, wr + WO_A21, ba2_1, nullptr, bufA, H_DIM, nullptr, nullptr);
    mma_gemm<128, 256, 0><<<gBig, 256, SM_BIG>>>(bufA, wr + WO_A22, ba2_2, bufB, out, H_DIM, nullptr, nullptr);
}

// round 14
// speedup vs baseline: 1.4405x; 1.0080x over previous
#include <cuda_runtime.h>
#include <cstdint>
#include <cstddef>

// ---------------- problem constants ----------------
static constexpr int E_EDGES = 131072;
static constexpr int T_TRIP  = 1048576;
static constexpr int H_DIM   = 256;
static constexpr int I_DIM   = 64;
static constexpr int NR      = 6;
static constexpr int NSR     = 42;
static constexpr int BAS     = 8;

// ---------------- scratch (static device memory) ----------------
__device__ float g_xji [(size_t)E_EDGES * H_DIM];
__device__ float g_bufA[(size_t)E_EDGES * H_DIM];
__device__ float g_bufB[(size_t)E_EDGES * H_DIM];
__device__ float g_xkjd[(size_t)E_EDGES * I_DIM];
__device__ float g_agg [(size_t)E_EDGES * I_DIM];
__device__ float g_s8t [(size_t)T_TRIP * BAS];
__device__ float g_s8e [(size_t)E_EDGES * BAS];
__device__ float g_wr  [622592];

// weight offsets inside g_wr
static constexpr int WO_JI   = 0;
static constexpr int WO_KJ   = 65536;
static constexpr int WO_B11  = 131072;
static constexpr int WO_B12  = 196608;
static constexpr int WO_LIN  = 262144;
static constexpr int WO_A11  = 327680;
static constexpr int WO_A12  = 393216;
static constexpr int WO_A21  = 458752;
static constexpr int WO_A22  = 524288;
static constexpr int WO_DOWN = 589824;
static constexpr int WO_UP   = 606208;

// ---------------- helpers ----------------
__device__ __forceinline__ uint32_t smem_to_u32(const void* p) {
    uint32_t a;
    asm("{ .reg .u64 t; cvta.to.shared.u64 t, %1; cvt.u32.u64 %0, t; }" : "=r"(a) : "l"(p));
    return a;
}
__device__ __forceinline__ uint32_t tf32r(float v) {
    uint32_t o; asm("cvt.rna.tf32.f32 %0, %1;" : "=r"(o) : "f"(v)); return o;
}
__device__ __forceinline__ float silu_f(float v) {
    return v * (1.0f / (1.0f + __expf(-v)));
}
__device__ __forceinline__ void cp_async16(uint32_t dst, const void* src) {
    asm volatile("cp.async.cg.shared.global [%0], [%1], 16;" :: "r"(dst), "l"(src));
}
__device__ __forceinline__ void mma_tf32(float d[4], const uint32_t a[4], const uint32_t b[2]) {
    asm volatile(
        "mma.sync.aligned.m16n8k8.row.col.f32.tf32.tf32.f32 "
        "{%0,%1,%2,%3}, {%4,%5,%6,%7}, {%8,%9}, {%0,%1,%2,%3};"
        : "+f"(d[0]), "+f"(d[1]), "+f"(d[2]), "+f"(d[3])
        : "r"(a[0]), "r"(a[1]), "r"(a[2]), "r"(a[3]), "r"(b[0]), "r"(b[1]));
}

// shared GEMM core config
static constexpr int BM_ = 128, BK_ = 32, DEPTH_ = 3;
static constexpr int AS_STRIDE_ = BK_ + 4;
static constexpr int AS_STAGE_  = BM_ * AS_STRIDE_;

// ============ mma.sync tf32 GEMM (R9 core, optional gate epilogue) ============
template <int BN, int K, int GATE>
__global__ void __launch_bounds__(256, 2)
mma_gemm(const float* __restrict__ A, const float* __restrict__ W,
         const float* __restrict__ bias, const float* __restrict__ res,
         float* __restrict__ C, int Nfull,
         const float* __restrict__ s8e, const float* __restrict__ Wg)
{
    constexpr int KT = K / BK_;
    constexpr int BS_STRIDE = BN + 8;
    constexpr int BS_STAGE  = BK_ * BS_STRIDE;
    constexpr int NF = BN / 16;

    extern __shared__ float smf[];
    float* As = smf;
    float* Bs = smf + DEPTH_ * AS_STAGE_;
    float* gWs = Bs + DEPTH_ * BS_STAGE;
    const uint32_t smemA = smem_to_u32(As);
    const uint32_t smemB = smem_to_u32(Bs);

    const int tid = threadIdx.x, lane = tid & 31, wid = tid >> 5;
    const int warpM = wid >> 1, warpN = wid & 1;
    const int row0 = blockIdx.y * BM_;
    const int col0 = blockIdx.x * BN;
    const int g = lane >> 2, q = lane & 3;

    if (GATE) {
        for (int i = tid; i < BAS * BN; i += 256) {
            int j = i / BN, n = i % BN;
            gWs[j * BN + n] = Wg[j * Nfull + col0 + n];
        }
    }

    float acc[2][NF][4];
#pragma unroll
    for (int mf = 0; mf < 2; mf++)
#pragma unroll
        for (int nf = 0; nf < NF; nf++)
#pragma unroll
            for (int v = 0; v < 4; v++) acc[mf][nf][v] = 0.0f;

    auto load_stage = [&](int s, int kt) {
        const int k0 = kt * BK_;
#pragma unroll
        for (int i = 0; i < 4; i++) {
            int id = tid + i * 256;
            int m = id >> 3, c4 = (id & 7) * 4;
            cp_async16(smemA + (uint32_t)(s * AS_STAGE_ + m * AS_STRIDE_ + c4) * 4,
                       A + (size_t)(row0 + m) * K + k0 + c4);
        }
        constexpr int BCH = BK_ * BN / 4;
#pragma unroll
        for (int i = 0; i < BCH / 256; i++) {
            int id = tid + i * 256;
            int k = id / (BN / 4), n4 = (id % (BN / 4)) * 4;
            cp_async16(smemB + (uint32_t)(s * BS_STAGE + k * BS_STRIDE + n4) * 4,
                       W + (size_t)(k0 + k) * Nfull + col0 + n4);
        }
    };

#pragma unroll
    for (int s = 0; s < DEPTH_ - 1; s++) {
        if (s < KT) load_stage(s, s);
        asm volatile("cp.async.commit_group;" ::: "memory");
    }

    for (int it = 0; it < KT; it++) {
        asm volatile("cp.async.wait_group %0;" :: "n"(DEPTH_ - 2) : "memory");
        __syncthreads();
        const int nx = it + DEPTH_ - 1;
        if (nx < KT) load_stage(nx % DEPTH_, nx);
        asm volatile("cp.async.commit_group;" ::: "memory");

        const int s = it % DEPTH_;
        const float* Asb = As + s * AS_STAGE_;
        const float* Bsb = Bs + s * BS_STAGE;
#pragma unroll
        for (int ks = 0; ks < 4; ks++) {
            uint32_t af[2][4];
            uint32_t bf[NF][2];
#pragma unroll
            for (int mf = 0; mf < 2; mf++) {
                int r = warpM * 32 + mf * 16 + g;
                af[mf][0] = __float_as_uint(Asb[r * AS_STRIDE_ + ks * 8 + q]);
                af[mf][1] = __float_as_uint(Asb[(r + 8) * AS_STRIDE_ + ks * 8 + q]);
                af[mf][2] = __float_as_uint(Asb[r * AS_STRIDE_ + ks * 8 + q + 4]);
                af[mf][3] = __float_as_uint(Asb[(r + 8) * AS_STRIDE_ + ks * 8 + q + 4]);
            }
#pragma unroll
            for (int nf = 0; nf < NF; nf++) {
                int c = warpN * (BN / 2) + nf * 8 + g;
                bf[nf][0] = __float_as_uint(Bsb[(ks * 8 + q) * BS_STRIDE + c]);
                bf[nf][1] = __float_as_uint(Bsb[(ks * 8 + q + 4) * BS_STRIDE + c]);
            }
#pragma unroll
            for (int mf = 0; mf < 2; mf++)
#pragma unroll
                for (int nf = 0; nf < NF; nf++)
                    mma_tf32(acc[mf][nf], af[mf], bf[nf]);
        }
    }

#pragma unroll
    for (int mf = 0; mf < 2; mf++) {
#pragma unroll
        for (int h = 0; h < 2; h++) {
            const int row = row0 + warpM * 32 + mf * 16 + g + h * 8;
            float4 se0, se1;
            if (GATE) {
                const float4* sp = reinterpret_cast<const float4*>(s8e + (size_t)row * BAS);
                se0 = __ldg(sp); se1 = __ldg(sp + 1);
            }
#pragma unroll
            for (int nf = 0; nf < NF; nf++) {
                const int cl = warpN * (BN / 2) + nf * 8 + 2 * q;
                const int col = col0 + cl;
                float bv0 = 0.0f, bv1 = 0.0f;
                if (bias) { bv0 = bias[col]; bv1 = bias[col + 1]; }
                float v0 = silu_f(acc[mf][nf][h * 2 + 0] + bv0);
                float v1 = silu_f(acc[mf][nf][h * 2 + 1] + bv1);
                if (GATE) {
                    float g0 = se0.x * gWs[0 * BN + cl] + se0.y * gWs[1 * BN + cl]
                             + se0.z * gWs[2 * BN + cl] + se0.w * gWs[3 * BN + cl]
                             + se1.x * gWs[4 * BN + cl] + se1.y * gWs[5 * BN + cl]
                             + se1.z * gWs[6 * BN + cl] + se1.w * gWs[7 * BN + cl];
                    float g1 = se0.x * gWs[0 * BN + cl + 1] + se0.y * gWs[1 * BN + cl + 1]
                             + se0.z * gWs[2 * BN + cl + 1] + se0.w * gWs[3 * BN + cl + 1]
                             + se1.x * gWs[4 * BN + cl + 1] + se1.y * gWs[5 * BN + cl + 1]
                             + se1.z * gWs[6 * BN + cl + 1] + se1.w * gWs[7 * BN + cl + 1];
                    v0 *= g0; v1 *= g1;
                }
                const size_t off = (size_t)row * Nfull + col;
                if (res) {
                    float2 r = *reinterpret_cast<const float2*>(res + off);
                    v0 += r.x; v1 += r.y;
                }
                uint2 o;
                o.x = tf32r(v0);
                o.y = tf32r(v1);
                *reinterpret_cast<uint2*>(C + off) = o;
            }
        }
    }
}

// ============ dual GEMM: kj (gated) + ji, shared A = x ============
__global__ void __launch_bounds__(256, 2)
dual_gemm(const float* __restrict__ A,
          const float* __restrict__ Wkj, const float* __restrict__ bkj,
          const float* __restrict__ Wji, const float* __restrict__ bji,
          float* __restrict__ Ckj, float* __restrict__ Cji,
          const float* __restrict__ s8e, const float* __restrict__ Wg)
{
    constexpr int BN = 128, K = 256, KT = K / BK_;
    constexpr int BS_STRIDE = BN + 8;
    constexpr int BS_STAGE  = BK_ * BS_STRIDE;
    constexpr int NF = BN / 16;

    extern __shared__ float smf[];
    float* As = smf;
    float* Bs = smf + DEPTH_ * AS_STAGE_;
    float* gWs = Bs + DEPTH_ * BS_STAGE;
    const uint32_t smemA = smem_to_u32(As);
    const uint32_t smemB = smem_to_u32(Bs);

    const int tid = threadIdx.x, lane = tid & 31, wid = tid >> 5;
    const int warpM = wid >> 1, warpN = wid & 1;
    const int row0 = blockIdx.y * BM_;
    const int is_ji = blockIdx.x >> 1;
    const int col0 = (blockIdx.x & 1) * BN;
    const int g = lane >> 2, q = lane & 3;

    const float* W    = is_ji ? Wji : Wkj;
    const float* bias = is_ji ? bji : bkj;
    float* C          = is_ji ? Cji : Ckj;

    if (!is_ji) {
        for (int i = tid; i < BAS * BN; i += 256) {
            int j = i / BN, n = i % BN;
            gWs[j * BN + n] = Wg[j * H_DIM + col0 + n];
        }
    }

    float acc[2][NF][4];
#pragma unroll
    for (int mf = 0; mf < 2; mf++)
#pragma unroll
        for (int nf = 0; nf < NF; nf++)
#pragma unroll
            for (int v = 0; v < 4; v++) acc[mf][nf][v] = 0.0f;

    auto load_stage = [&](int s, int kt) {
        const int k0 = kt * BK_;
#pragma unroll
        for (int i = 0; i < 4; i++) {
            int id = tid + i * 256;
            int m = id >> 3, c4 = (id & 7) * 4;
            cp_async16(smemA + (uint32_t)(s * AS_STAGE_ + m * AS_STRIDE_ + c4) * 4,
                       A + (size_t)(row0 + m) * K + k0 + c4);
        }
        constexpr int BCH = BK_ * BN / 4;
#pragma unroll
        for (int i = 0; i < BCH / 256; i++) {
            int id = tid + i * 256;
            int k = id / (BN / 4), n4 = (id % (BN / 4)) * 4;
            cp_async16(smemB + (uint32_t)(s * BS_STAGE + k * BS_STRIDE + n4) * 4,
                       W + (size_t)(k0 + k) * H_DIM + col0 + n4);
        }
    };

#pragma unroll
    for (int s = 0; s < DEPTH_ - 1; s++) {
        load_stage(s, s);
        asm volatile("cp.async.commit_group;" ::: "memory");
    }

    for (int it = 0; it < KT; it++) {
        asm volatile("cp.async.wait_group %0;" :: "n"(DEPTH_ - 2) : "memory");
        __syncthreads();
        const int nx = it + DEPTH_ - 1;
        if (nx < KT) load_stage(nx % DEPTH_, nx);
        asm volatile("cp.async.commit_group;" ::: "memory");

        const int s = it % DEPTH_;
        const float* Asb = As + s * AS_STAGE_;
        const float* Bsb = Bs + s * BS_STAGE;
#pragma unroll
        for (int ks = 0; ks < 4; ks++) {
            uint32_t af[2][4];
            uint32_t bf[NF][2];
#pragma unroll
            for (int mf = 0; mf < 2; mf++) {
                int r = warpM * 32 + mf * 16 + g;
                af[mf][0] = __float_as_uint(Asb[r * AS_STRIDE_ + ks * 8 + q]);
                af[mf][1] = __float_as_uint(Asb[(r + 8) * AS_STRIDE_ + ks * 8 + q]);
                af[mf][2] = __float_as_uint(Asb[r * AS_STRIDE_ + ks * 8 + q + 4]);
                af[mf][3] = __float_as_uint(Asb[(r + 8) * AS_STRIDE_ + ks * 8 + q + 4]);
            }
#pragma unroll
            for (int nf = 0; nf < NF; nf++) {
                int c = warpN * (BN / 2) + nf * 8 + g;
                bf[nf][0] = __float_as_uint(Bsb[(ks * 8 + q) * BS_STRIDE + c]);
                bf[nf][1] = __float_as_uint(Bsb[(ks * 8 + q + 4) * BS_STRIDE + c]);
            }
#pragma unroll
            for (int mf = 0; mf < 2; mf++)
#pragma unroll
                for (int nf = 0; nf < NF; nf++)
                    mma_tf32(acc[mf][nf], af[mf], bf[nf]);
        }
    }

#pragma unroll
    for (int mf = 0; mf < 2; mf++) {
#pragma unroll
        for (int h = 0; h < 2; h++) {
            const int row = row0 + warpM * 32 + mf * 16 + g + h * 8;
            float4 se0 = make_float4(0, 0, 0, 0), se1 = make_float4(0, 0, 0, 0);
            if (!is_ji) {
                const float4* sp = reinterpret_cast<const float4*>(s8e + (size_t)row * BAS);
                se0 = __ldg(sp); se1 = __ldg(sp + 1);
            }
#pragma unroll
            for (int nf = 0; nf < NF; nf++) {
                const int cl = warpN * (BN / 2) + nf * 8 + 2 * q;
                const int col = col0 + cl;
                float v0 = silu_f(acc[mf][nf][h * 2 + 0] + bias[col]);
                float v1 = silu_f(acc[mf][nf][h * 2 + 1] + bias[col + 1]);
                if (!is_ji) {
                    float g0 = se0.x * gWs[0 * BN + cl] + se0.y * gWs[1 * BN + cl]
                             + se0.z * gWs[2 * BN + cl] + se0.w * gWs[3 * BN + cl]
                             + se1.x * gWs[4 * BN + cl] + se1.y * gWs[5 * BN + cl]
                             + se1.z * gWs[6 * BN + cl] + se1.w * gWs[7 * BN + cl];
                    float g1 = se0.x * gWs[0 * BN + cl + 1] + se0.y * gWs[1 * BN + cl + 1]
                             + se0.z * gWs[2 * BN + cl + 1] + se0.w * gWs[3 * BN + cl + 1]
                             + se1.x * gWs[4 * BN + cl + 1] + se1.y * gWs[5 * BN + cl + 1]
                             + se1.z * gWs[6 * BN + cl + 1] + se1.w * gWs[7 * BN + cl + 1];
                    v0 *= g0; v1 *= g1;
                }
                const size_t off = (size_t)row * H_DIM + col;
                uint2 o;
                o.x = tf32r(v0);
                o.y = tf32r(v1);
                *reinterpret_cast<uint2*>(C + off) = o;
            }
        }
    }
}

static constexpr int mma_smem(int BN, int gate) {
    return (3 * (128 * 36 + 32 * (BN + 8)) + (gate ? 8 * BN : 0)) * 4;
}

// ============ merged setup: round_w + s8e + s8t + zero(agg) in one launch ============
struct WSet { const float* src[11]; float* dst[11]; int n4[11]; };
static constexpr int SB_RW  = 176;                 // 11 segs x 16 blocks
static constexpr int SB_S8E = SB_RW + 512;         // 512 x 256 = E
static constexpr int SB_S8T = SB_S8E + 4096;       // 4096 x 256 = T
static constexpr int SB_ZERO = SB_S8T + 1024;      // 1024 blocks zero
__global__ void setup_kernel(WSet ws,
                             const float* __restrict__ rbf, const float* __restrict__ Wr1,
                             float* __restrict__ s8e,
                             const float* __restrict__ sbf, const float* __restrict__ Ws1,
                             float* __restrict__ s8t,
                             float4* __restrict__ agg4)
{
    __shared__ float w[NSR * BAS];   // 336 floats, reused per segment
    const int b = blockIdx.x, tid = threadIdx.x;

    if (b < SB_RW) {
        int seg = b >> 4, blk = b & 15;
        const float4* s = reinterpret_cast<const float4*>(ws.src[seg]);
        float4* d = reinterpret_cast<float4*>(ws.dst[seg]);
        int n4 = ws.n4[seg];
        for (int i = blk * 256 + tid; i < n4; i += 16 * 256) {
            float4 v = s[i];
            uint4 o;
            o.x = tf32r(v.x); o.y = tf32r(v.y); o.z = tf32r(v.z); o.w = tf32r(v.w);
            *reinterpret_cast<uint4*>(&d[i]) = o;
        }
    } else if (b < SB_S8E) {
        if (tid < NR * BAS) w[tid] = Wr1[tid];
        __syncthreads();
        int e = (b - SB_RW) * 256 + tid;
        float r[NR];
#pragma unroll
        for (int i = 0; i < NR; i++) r[i] = __ldg(rbf + (size_t)e * NR + i);
        float o[BAS];
#pragma unroll
        for (int j = 0; j < BAS; j++) {
            float s = 0.f;
#pragma unroll
            for (int i = 0; i < NR; i++) s += r[i] * w[i * BAS + j];
            o[j] = s;
        }
        reinterpret_cast<float4*>(s8e)[e * 2 + 0] = make_float4(o[0], o[1], o[2], o[3]);
        reinterpret_cast<float4*>(s8e)[e * 2 + 1] = make_float4(o[4], o[5], o[6], o[7]);
    } else if (b < SB_S8T) {
        for (int i = tid; i < NSR * BAS; i += 256) w[i] = Ws1[i];
        __syncthreads();
        int t = (b - SB_S8E) * 256 + tid;
        const float* srow = sbf + (size_t)t * NSR;
        float o[BAS];
#pragma unroll
        for (int j = 0; j < BAS; j++) o[j] = 0.0f;
#pragma unroll
        for (int i = 0; i < NSR; i++) {
            float r = __ldg(srow + i);
#pragma unroll
            for (int j = 0; j < BAS; j++) o[j] += r * w[i * BAS + j];
        }
        reinterpret_cast<float4*>(s8t)[(size_t)t * 2 + 0] = make_float4(o[0], o[1], o[2], o[3]);
        reinterpret_cast<float4*>(s8t)[(size_t)t * 2 + 1] = make_float4(o[4], o[5], o[6], o[7]);
    } else {
        const int n4 = E_EDGES * I_DIM / 4;
        for (int i = (b - SB_S8T) * 256 + tid; i < n4; i += 1024 * 256)
            agg4[i] = make_float4(0, 0, 0, 0);
    }
}

// ---------------- triplet pass: 2x ILP unroll ----------------
// T/2 iterations per warp = 32, evenly divisible by 2 with nwarp = 16384.
__global__ void triplet_kernel(const float* __restrict__ s8t,
                               const int* __restrict__ idx_kj,
                               const int* __restrict__ idx_ji,
                               const float* __restrict__ W2,
                               const float* __restrict__ xkjd,
                               float* __restrict__ agg)
{
    __shared__ __align__(16) float sW2[BAS * I_DIM];
    for (int i = threadIdx.x; i < BAS * I_DIM; i += blockDim.x) sW2[i] = W2[i];
    __syncthreads();

    const int lane  = threadIdx.x & 31;
    const int wglob = (blockIdx.x * blockDim.x + threadIdx.x) >> 5;
    const int nwarp = (gridDim.x * blockDim.x) >> 5;
    const int sub = lane >> 4;
    const int sl  = lane & 15;
    const int c   = sl * 4;

    // preload W2 fragments for this lane's 4 columns (register-resident, reused every iter)
    float4 wf[BAS];
#pragma unroll
    for (int jj = 0; jj < BAS; jj++)
        wf[jj] = *reinterpret_cast<const float4*>(&sW2[jj * I_DIM + c]);

    for (int p = wglob; (p + nwarp) * 2 <= T_TRIP; p += 2 * nwarp) {
        const int t0 = p * 2 + sub;
        const int t1 = (p + nwarp) * 2 + sub;
        // batch all loads: two independent gather chains in flight
        const float4* s8p0 = reinterpret_cast<const float4*>(s8t + (size_t)t0 * BAS);
        const float4* s8p1 = reinterpret_cast<const float4*>(s8t + (size_t)t1 * BAS);
        float4 a0 = __ldg(s8p0), a1 = __ldg(s8p0 + 1);
        float4 b0 = __ldg(s8p1), b1 = __ldg(s8p1 + 1);
        int ekj0 = __ldg(idx_kj + t0), eji0 = __ldg(idx_ji + t0);
        int ekj1 = __ldg(idx_kj + t1), eji1 = __ldg(idx_ji + t1);
        float4 xv0 = __ldg(reinterpret_cast<const float4*>(&xkjd[(size_t)ekj0 * I_DIM + c]));
        float4 xv1 = __ldg(reinterpret_cast<const float4*>(&xkjd[(size_t)ekj1 * I_DIM + c]));

        float4 m0 = make_float4(0, 0, 0, 0), m1 = make_float4(0, 0, 0, 0);
        float s0[BAS] = {a0.x, a0.y, a0.z, a0.w, a1.x, a1.y, a1.z, a1.w};
        float s1[BAS] = {b0.x, b0.y, b0.z, b0.w, b1.x, b1.y, b1.z, b1.w};
#pragma unroll
        for (int jj = 0; jj < BAS; jj++) {
            m0.x += s0[jj] * wf[jj].x; m0.y += s0[jj] * wf[jj].y;
            m0.z += s0[jj] * wf[jj].z; m0.w += s0[jj] * wf[jj].w;
            m1.x += s1[jj] * wf[jj].x; m1.y += s1[jj] * wf[jj].y;
            m1.z += s1[jj] * wf[jj].z; m1.w += s1[jj] * wf[jj].w;
        }
        m0.x *= xv0.x; m0.y *= xv0.y; m0.z *= xv0.z; m0.w *= xv0.w;
        m1.x *= xv1.x; m1.y *= xv1.y; m1.z *= xv1.z; m1.w *= xv1.w;
        atomicAdd(reinterpret_cast<float4*>(&agg[(size_t)eji0 * I_DIM + c]), m0);
        atomicAdd(reinterpret_cast<float4*>(&agg[(size_t)eji1 * I_DIM + c]), m1);
    }
}

// ---------------- launch ----------------
extern "C" void kernel_launch(void* const* d_in, const int* in_sizes, int n_in,
                              void* d_out, int out_size)
{
    const float* x      = (const float*)d_in[0];
    const float* rbf    = (const float*)d_in[1];
    const float* sbf    = (const float*)d_in[2];
    const int*   idx_kj = (const int*)d_in[3];
    const int*   idx_ji = (const int*)d_in[4];
    const float* W_ji   = (const float*)d_in[5];
    const float* b_ji   = (const float*)d_in[6];
    const float* W_kj   = (const float*)d_in[7];
    const float* b_kj   = (const float*)d_in[8];
    const float* W_rbf1 = (const float*)d_in[9];
    const float* W_rbf2 = (const float*)d_in[10];
    const float* W_sbf1 = (const float*)d_in[11];
    const float* W_sbf2 = (const float*)d_in[12];
    const float* W_down = (const float*)d_in[13];
    const float* W_up   = (const float*)d_in[14];
    const float* Wb1_1  = (const float*)d_in[15];
    const float* bb1_1  = (const float*)d_in[16];
    const float* Wb1_2  = (const float*)d_in[17];
    const float* bb1_2  = (const float*)d_in[18];
    const float* W_lin  = (const float*)d_in[19];
    const float* b_lin  = (const float*)d_in[20];
    const float* Wa1_1  = (const float*)d_in[21];
    const float* ba1_1  = (const float*)d_in[22];
    const float* Wa1_2  = (const float*)d_in[23];
    const float* ba1_2  = (const float*)d_in[24];
    const float* Wa2_1  = (const float*)d_in[25];
    const float* ba2_1  = (const float*)d_in[26];
    const float* Wa2_2  = (const float*)d_in[27];
    const float* ba2_2  = (const float*)d_in[28];
    float* out = (float*)d_out;

    float *xji, *bufA, *bufB, *xkjd, *agg, *s8t, *s8e, *wr;
    cudaGetSymbolAddress((void**)&xji,  g_xji);
    cudaGetSymbolAddress((void**)&bufA, g_bufA);
    cudaGetSymbolAddress((void**)&bufB, g_bufB);
    cudaGetSymbolAddress((void**)&xkjd, g_xkjd);
    cudaGetSymbolAddress((void**)&agg,  g_agg);
    cudaGetSymbolAddress((void**)&s8t,  g_s8t);
    cudaGetSymbolAddress((void**)&s8e,  g_s8e);
    cudaGetSymbolAddress((void**)&wr,   g_wr);

    constexpr int SM_BIG   = mma_smem(128, 0);
    constexpr int SM_GATE  = mma_smem(128, 1);
    constexpr int SM_DOWN  = mma_smem(64, 0);
    cudaFuncSetAttribute(mma_gemm<128, 256, 0>, cudaFuncAttributeMaxDynamicSharedMemorySize, SM_BIG);
    cudaFuncSetAttribute(mma_gemm<64, 256, 0>,  cudaFuncAttributeMaxDynamicSharedMemorySize, SM_DOWN);
    cudaFuncSetAttribute(mma_gemm<128, 64, 0>,  cudaFuncAttributeMaxDynamicSharedMemorySize, SM_BIG);
    cudaFuncSetAttribute(dual_gemm,             cudaFuncAttributeMaxDynamicSharedMemorySize, SM_GATE);

    const dim3 gBig(2, E_EDGES / 128);
    const dim3 gDown(1, E_EDGES / 128);
    const dim3 gDual(4, E_EDGES / 128);

    WSet ws;
    const float* srcs[11] = {W_ji, W_kj, Wb1_1, Wb1_2, W_lin, Wa1_1, Wa1_2, Wa2_1, Wa2_2, W_down, W_up};
    const int offs[11]    = {WO_JI, WO_KJ, WO_B11, WO_B12, WO_LIN, WO_A11, WO_A12, WO_A21, WO_A22, WO_DOWN, WO_UP};
    const int n4s[11]     = {16384, 16384, 16384, 16384, 16384, 16384, 16384, 16384, 16384, 4096, 4096};
    for (int i = 0; i < 11; i++) { ws.src[i] = srcs[i]; ws.dst[i] = wr + offs[i]; ws.n4[i] = n4s[i]; }

    // 0: setup (weights round + s8e + s8t + zero agg), one launch
    setup_kernel<<<SB_ZERO, 256>>>(ws, rbf, W_rbf1, s8e, sbf, W_sbf1, s8t, (float4*)agg);
    // 1: dual: x_kj_gated -> bufA, x_ji -> xji
    dual_gemm<<<gDual, 256, SM_GATE>>>(x, wr + WO_KJ, b_kj, wr + WO_JI, b_ji,
                                       bufA, xji, s8e, W_rbf2);
    // 2: x_kj_down = silu(x_kj_gated @ W_down)
    mma_gemm<64, 256, 0><<<gDown, 256, SM_DOWN>>>(bufA, wr + WO_DOWN, nullptr, nullptr, xkjd, I_DIM, nullptr, nullptr);
    // 3: triplet message passing   <- ncu profile slot
    triplet_kernel<<<2048, 256>>>(s8t, idx_kj, idx_ji, W_sbf2, xkjd, agg);
    // 4: h = x_ji + silu(agg @ W_up)
    mma_gemm<128, 64, 0><<<gBig, 256, SM_BIG>>>(agg, wr + WO_UP, nullptr, xji, bufA, H_DIM, nullptr, nullptr);
    // 5-6: pre-skip residual pair
    mma_gemm<128, 256, 0><<<gBig, 256, SM_BIG>>>(bufA, wr + WO_B11, bb1_1, nullptr, bufB, H_DIM, nullptr, nullptr);
    mma_gemm<128, 256, 0><<<gBig, 256, SM_BIG>>>(bufB, wr + WO_B12, bb1_2, bufA, bufA, H_DIM, nullptr, nullptr);
    // 7: skip: h = silu(h@W_lin+b) + x
    mma_gemm<128, 256, 0><<<gBig, 256, SM_BIG>>>(bufA, wr + WO_LIN, b_lin, x, bufB, H_DIM, nullptr, nullptr);
    // 8-9: post-skip residual pair 1
    mma_gemm<128, 256, 0><<<gBig, 256, SM_BIG>>>(bufB, wr + WO_A11, ba1_1, nullptr, bufA, H_DIM, nullptr, nullptr);
    mma_gemm<128, 256, 0><<<gBig, 256, SM_BIG>>>(bufA, wr + WO_A12, ba1_2, bufB, bufB, H_DIM, nullptr, nullptr);
    // 10-11: post-skip residual pair 2 -> final output
    mma_gemm<128, 256, 0><<<gBig, 256, SM_BIG>>>(bufB, wr + WO_A21, ba2_1, nullptr, bufA, H_DIM, nullptr, nullptr);
    mma_gemm<128, 256, 0><<<gBig, 256, SM_BIG>>>(bufA, wr + WO_A22, ba2_2, bufB, out, H_DIM, nullptr, nullptr);
}

// round 15
// speedup vs baseline: 1.4405x; 1.0000x over previous
#include <cuda_runtime.h>
#include <cstdint>
#include <cstddef>

// ---------------- problem constants ----------------
static constexpr int E_EDGES = 131072;
static constexpr int T_TRIP  = 1048576;
static constexpr int H_DIM   = 256;
static constexpr int I_DIM   = 64;
static constexpr int NR      = 6;
static constexpr int NSR     = 42;
static constexpr int BAS     = 8;

// ---------------- scratch (static device memory) ----------------
__device__ float g_xji [(size_t)E_EDGES * H_DIM];
__device__ float g_bufA[(size_t)E_EDGES * H_DIM];
__device__ float g_bufB[(size_t)E_EDGES * H_DIM];
__device__ float g_xkjd[(size_t)E_EDGES * I_DIM];
__device__ float g_agg [(size_t)E_EDGES * I_DIM];
__device__ float g_s8t [(size_t)T_TRIP * BAS];
__device__ float g_s8e [(size_t)E_EDGES * BAS];
__device__ float g_wr  [622592];

static constexpr int WO_JI   = 0;
static constexpr int WO_KJ   = 65536;
static constexpr int WO_B11  = 131072;
static constexpr int WO_B12  = 196608;
static constexpr int WO_LIN  = 262144;
static constexpr int WO_A11  = 327680;
static constexpr int WO_A12  = 393216;
static constexpr int WO_A21  = 458752;
static constexpr int WO_A22  = 524288;
static constexpr int WO_DOWN = 589824;
static constexpr int WO_UP   = 606208;

// ---------------- helpers ----------------
__device__ __forceinline__ uint32_t smem_to_u32(const void* p) {
    uint32_t a;
    asm("{ .reg .u64 t; cvta.to.shared.u64 t, %1; cvt.u32.u64 %0, t; }" : "=r"(a) : "l"(p));
    return a;
}
__device__ __forceinline__ uint32_t tf32r(float v) {
    uint32_t o; asm("cvt.rna.tf32.f32 %0, %1;" : "=r"(o) : "f"(v)); return o;
}
__device__ __forceinline__ float silu_f(float v) {
    return v * (1.0f / (1.0f + __expf(-v)));
}
__device__ __forceinline__ void cp_async16(uint32_t dst, const void* src) {
    asm volatile("cp.async.cg.shared.global [%0], [%1], 16;" :: "r"(dst), "l"(src));
}
__device__ __forceinline__ void mma_tf32(float d[4], const uint32_t a[4], const uint32_t b[2]) {
    asm volatile(
        "mma.sync.aligned.m16n8k8.row.col.f32.tf32.tf32.f32 "
        "{%0,%1,%2,%3}, {%4,%5,%6,%7}, {%8,%9}, {%0,%1,%2,%3};"
        : "+f"(d[0]), "+f"(d[1]), "+f"(d[2]), "+f"(d[3])
        : "r"(a[0]), "r"(a[1]), "r"(a[2]), "r"(a[3]), "r"(b[0]), "r"(b[1]));
}
__device__ __forceinline__ void pdl_sync() {
#if __CUDA_ARCH__ >= 900
    cudaGridDependencySynchronize();
#endif
}
__device__ __forceinline__ void pdl_trigger() {
#if __CUDA_ARCH__ >= 900
    cudaTriggerProgrammaticLaunchCompletion();
#endif
}

static constexpr int BM_ = 128, BK_ = 32, DEPTH_ = 3;
static constexpr int AS_STRIDE_ = BK_ + 4;
static constexpr int AS_STAGE_  = BM_ * AS_STRIDE_;

// ============ mma.sync tf32 GEMM (R9 core) + PDL ============
// W/bias/gWs are "stable" inputs (written >=2 kernels earlier) -> loaded before
// cudaGridDependencySynchronize(); A (predecessor's output) loaded after.
template <int BN, int K, int GATE>
__global__ void __launch_bounds__(256, 2)
mma_gemm(const float* __restrict__ A, const float* __restrict__ W,
         const float* __restrict__ bias, const float* __restrict__ res,
         float* __restrict__ C, int Nfull,
         const float* __restrict__ s8e, const float* __restrict__ Wg)
{
    constexpr int KT = K / BK_;
    constexpr int BS_STRIDE = BN + 8;
    constexpr int BS_STAGE  = BK_ * BS_STRIDE;
    constexpr int NF = BN / 16;

    extern __shared__ float smf[];
    float* As = smf;
    float* Bs = smf + DEPTH_ * AS_STAGE_;
    float* gWs = Bs + DEPTH_ * BS_STAGE;
    const uint32_t smemA = smem_to_u32(As);
    const uint32_t smemB = smem_to_u32(Bs);

    const int tid = threadIdx.x, lane = tid & 31, wid = tid >> 5;
    const int warpM = wid >> 1, warpN = wid & 1;
    const int row0 = blockIdx.y * BM_;
    const int col0 = blockIdx.x * BN;
    const int g = lane >> 2, q = lane & 3;

    auto loadW = [&](int s, int kt) {
        const int k0 = kt * BK_;
        constexpr int BCH = BK_ * BN / 4;
#pragma unroll
        for (int i = 0; i < BCH / 256; i++) {
            int id = tid + i * 256;
            int k = id / (BN / 4), n4 = (id % (BN / 4)) * 4;
            cp_async16(smemB + (uint32_t)(s * BS_STAGE + k * BS_STRIDE + n4) * 4,
                       W + (size_t)(k0 + k) * Nfull + col0 + n4);
        }
    };
    auto loadA = [&](int s, int kt) {
        const int k0 = kt * BK_;
#pragma unroll
        for (int i = 0; i < 4; i++) {
            int id = tid + i * 256;
            int m = id >> 3, c4 = (id & 7) * 4;
            cp_async16(smemA + (uint32_t)(s * AS_STAGE_ + m * AS_STRIDE_ + c4) * 4,
                       A + (size_t)(row0 + m) * K + k0 + c4);
        }
    };

    // --- pre-sync: stable data only ---
    if (GATE) {
        for (int i = tid; i < BAS * BN; i += 256) {
            int j = i / BN, n = i % BN;
            gWs[j * BN + n] = Wg[j * Nfull + col0 + n];
        }
    }
#pragma unroll
    for (int s = 0; s < DEPTH_ - 1; s++)
        if (s < KT) loadW(s, s);

    pdl_sync();      // predecessor grid complete; its writes visible
    pdl_trigger();   // let successor's blocks schedule into our tail

    float acc[2][NF][4];
#pragma unroll
    for (int mf = 0; mf < 2; mf++)
#pragma unroll
        for (int nf = 0; nf < NF; nf++)
#pragma unroll
            for (int v = 0; v < 4; v++) acc[mf][nf][v] = 0.0f;

    // group0 = {W0,W1,A0}, group1 = {A1}
#pragma unroll
    for (int s = 0; s < DEPTH_ - 1; s++) {
        if (s < KT) loadA(s, s);
        asm volatile("cp.async.commit_group;" ::: "memory");
    }

    for (int it = 0; it < KT; it++) {
        asm volatile("cp.async.wait_group %0;" :: "n"(DEPTH_ - 2) : "memory");
        __syncthreads();
        const int nx = it + DEPTH_ - 1;
        if (nx < KT) { loadA(nx % DEPTH_, nx); loadW(nx % DEPTH_, nx); }
        asm volatile("cp.async.commit_group;" ::: "memory");

        const int s = it % DEPTH_;
        const float* Asb = As + s * AS_STAGE_;
        const float* Bsb = Bs + s * BS_STAGE;
#pragma unroll
        for (int ks = 0; ks < 4; ks++) {
            uint32_t af[2][4];
            uint32_t bf[NF][2];
#pragma unroll
            for (int mf = 0; mf < 2; mf++) {
                int r = warpM * 32 + mf * 16 + g;
                af[mf][0] = __float_as_uint(Asb[r * AS_STRIDE_ + ks * 8 + q]);
                af[mf][1] = __float_as_uint(Asb[(r + 8) * AS_STRIDE_ + ks * 8 + q]);
                af[mf][2] = __float_as_uint(Asb[r * AS_STRIDE_ + ks * 8 + q + 4]);
                af[mf][3] = __float_as_uint(Asb[(r + 8) * AS_STRIDE_ + ks * 8 + q + 4]);
            }
#pragma unroll
            for (int nf = 0; nf < NF; nf++) {
                int c = warpN * (BN / 2) + nf * 8 + g;
                bf[nf][0] = __float_as_uint(Bsb[(ks * 8 + q) * BS_STRIDE + c]);
                bf[nf][1] = __float_as_uint(Bsb[(ks * 8 + q + 4) * BS_STRIDE + c]);
            }
#pragma unroll
            for (int mf = 0; mf < 2; mf++)
#pragma unroll
                for (int nf = 0; nf < NF; nf++)
                    mma_tf32(acc[mf][nf], af[mf], bf[nf]);
        }
    }

#pragma unroll
    for (int mf = 0; mf < 2; mf++) {
#pragma unroll
        for (int h = 0; h < 2; h++) {
            const int row = row0 + warpM * 32 + mf * 16 + g + h * 8;
            float4 se0, se1;
            if (GATE) {
                const float4* sp = reinterpret_cast<const float4*>(s8e + (size_t)row * BAS);
                se0 = __ldg(sp); se1 = __ldg(sp + 1);
            }
#pragma unroll
            for (int nf = 0; nf < NF; nf++) {
                const int cl = warpN * (BN / 2) + nf * 8 + 2 * q;
                const int col = col0 + cl;
                float bv0 = 0.0f, bv1 = 0.0f;
                if (bias) { bv0 = bias[col]; bv1 = bias[col + 1]; }
                float v0 = silu_f(acc[mf][nf][h * 2 + 0] + bv0);
                float v1 = silu_f(acc[mf][nf][h * 2 + 1] + bv1);
                if (GATE) {
                    float g0 = se0.x * gWs[0 * BN + cl] + se0.y * gWs[1 * BN + cl]
                             + se0.z * gWs[2 * BN + cl] + se0.w * gWs[3 * BN + cl]
                             + se1.x * gWs[4 * BN + cl] + se1.y * gWs[5 * BN + cl]
                             + se1.z * gWs[6 * BN + cl] + se1.w * gWs[7 * BN + cl];
                    float g1 = se0.x * gWs[0 * BN + cl + 1] + se0.y * gWs[1 * BN + cl + 1]
                             + se0.z * gWs[2 * BN + cl + 1] + se0.w * gWs[3 * BN + cl + 1]
                             + se1.x * gWs[4 * BN + cl + 1] + se1.y * gWs[5 * BN + cl + 1]
                             + se1.z * gWs[6 * BN + cl + 1] + se1.w * gWs[7 * BN + cl + 1];
                    v0 *= g0; v1 *= g1;
                }
                const size_t off = (size_t)row * Nfull + col;
                if (res) {
                    float2 r = *reinterpret_cast<const float2*>(res + off);
                    v0 += r.x; v1 += r.y;
                }
                uint2 o;
                o.x = tf32r(v0);
                o.y = tf32r(v1);
                *reinterpret_cast<uint2*>(C + off) = o;
            }
        }
    }
}

// ============ dual GEMM: kj (gated) + ji, shared A = x, PDL ============
__global__ void __launch_bounds__(256, 2)
dual_gemm(const float* __restrict__ A,
          const float* __restrict__ Wkj, const float* __restrict__ bkj,
          const float* __restrict__ Wji, const float* __restrict__ bji,
          float* __restrict__ Ckj, float* __restrict__ Cji,
          const float* __restrict__ s8e, const float* __restrict__ Wg)
{
    constexpr int BN = 128, K = 256, KT = K / BK_;
    constexpr int BS_STRIDE = BN + 8;
    constexpr int BS_STAGE  = BK_ * BS_STRIDE;
    constexpr int NF = BN / 16;

    extern __shared__ float smf[];
    float* As = smf;
    float* Bs = smf + DEPTH_ * AS_STAGE_;
    float* gWs = Bs + DEPTH_ * BS_STAGE;
    const uint32_t smemA = smem_to_u32(As);
    const uint32_t smemB = smem_to_u32(Bs);

    const int tid = threadIdx.x, lane = tid & 31, wid = tid >> 5;
    const int warpM = wid >> 1, warpN = wid & 1;
    const int row0 = blockIdx.y * BM_;
    const int is_ji = blockIdx.x >> 1;
    const int col0 = (blockIdx.x & 1) * BN;
    const int g = lane >> 2, q = lane & 3;

    const float* W    = is_ji ? Wji : Wkj;
    const float* bias = is_ji ? bji : bkj;
    float* C          = is_ji ? Cji : Ckj;

    auto loadW = [&](int s, int kt) {
        const int k0 = kt * BK_;
        constexpr int BCH = BK_ * BN / 4;
#pragma unroll
        for (int i = 0; i < BCH / 256; i++) {
            int id = tid + i * 256;
            int k = id / (BN / 4), n4 = (id % (BN / 4)) * 4;
            cp_async16(smemB + (uint32_t)(s * BS_STAGE + k * BS_STRIDE + n4) * 4,
                       W + (size_t)(k0 + k) * H_DIM + col0 + n4);
        }
    };
    auto loadA = [&](int s, int kt) {
        const int k0 = kt * BK_;
#pragma unroll
        for (int i = 0; i < 4; i++) {
            int id = tid + i * 256;
            int m = id >> 3, c4 = (id & 7) * 4;
            cp_async16(smemA + (uint32_t)(s * AS_STAGE_ + m * AS_STRIDE_ + c4) * 4,
                       A + (size_t)(row0 + m) * K + k0 + c4);
        }
    };

    if (!is_ji) {
        for (int i = tid; i < BAS * BN; i += 256) {
            int j = i / BN, n = i % BN;
            gWs[j * BN + n] = Wg[j * H_DIM + col0 + n];
        }
    }
#pragma unroll
    for (int s = 0; s < DEPTH_ - 1; s++) loadW(s, s);

    pdl_sync();
    pdl_trigger();

    float acc[2][NF][4];
#pragma unroll
    for (int mf = 0; mf < 2; mf++)
#pragma unroll
        for (int nf = 0; nf < NF; nf++)
#pragma unroll
            for (int v = 0; v < 4; v++) acc[mf][nf][v] = 0.0f;

#pragma unroll
    for (int s = 0; s < DEPTH_ - 1; s++) {
        loadA(s, s);
        asm volatile("cp.async.commit_group;" ::: "memory");
    }

    for (int it = 0; it < KT; it++) {
        asm volatile("cp.async.wait_group %0;" :: "n"(DEPTH_ - 2) : "memory");
        __syncthreads();
        const int nx = it + DEPTH_ - 1;
        if (nx < KT) { loadA(nx % DEPTH_, nx); loadW(nx % DEPTH_, nx); }
        asm volatile("cp.async.commit_group;" ::: "memory");

        const int s = it % DEPTH_;
        const float* Asb = As + s * AS_STAGE_;
        const float* Bsb = Bs + s * BS_STAGE;
#pragma unroll
        for (int ks = 0; ks < 4; ks++) {
            uint32_t af[2][4];
            uint32_t bf[NF][2];
#pragma unroll
            for (int mf = 0; mf < 2; mf++) {
                int r = warpM * 32 + mf * 16 + g;
                af[mf][0] = __float_as_uint(Asb[r * AS_STRIDE_ + ks * 8 + q]);
                af[mf][1] = __float_as_uint(Asb[(r + 8) * AS_STRIDE_ + ks * 8 + q]);
                af[mf][2] = __float_as_uint(Asb[r * AS_STRIDE_ + ks * 8 + q + 4]);
                af[mf][3] = __float_as_uint(Asb[(r + 8) * AS_STRIDE_ + ks * 8 + q + 4]);
            }
#pragma unroll
            for (int nf = 0; nf < NF; nf++) {
                int c = warpN * (BN / 2) + nf * 8 + g;
                bf[nf][0] = __float_as_uint(Bsb[(ks * 8 + q) * BS_STRIDE + c]);
                bf[nf][1] = __float_as_uint(Bsb[(ks * 8 + q + 4) * BS_STRIDE + c]);
            }
#pragma unroll
            for (int mf = 0; mf < 2; mf++)
#pragma unroll
                for (int nf = 0; nf < NF; nf++)
                    mma_tf32(acc[mf][nf], af[mf], bf[nf]);
        }
    }

#pragma unroll
    for (int mf = 0; mf < 2; mf++) {
#pragma unroll
        for (int h = 0; h < 2; h++) {
            const int row = row0 + warpM * 32 + mf * 16 + g + h * 8;
            float4 se0 = make_float4(0, 0, 0, 0), se1 = make_float4(0, 0, 0, 0);
            if (!is_ji) {
                const float4* sp = reinterpret_cast<const float4*>(s8e + (size_t)row * BAS);
                se0 = __ldg(sp); se1 = __ldg(sp + 1);
            }
#pragma unroll
            for (int nf = 0; nf < NF; nf++) {
                const int cl = warpN * (BN / 2) + nf * 8 + 2 * q;
                const int col = col0 + cl;
                float v0 = silu_f(acc[mf][nf][h * 2 + 0] + bias[col]);
                float v1 = silu_f(acc[mf][nf][h * 2 + 1] + bias[col + 1]);
                if (!is_ji) {
                    float g0 = se0.x * gWs[0 * BN + cl] + se0.y * gWs[1 * BN + cl]
                             + se0.z * gWs[2 * BN + cl] + se0.w * gWs[3 * BN + cl]
                             + se1.x * gWs[4 * BN + cl] + se1.y * gWs[5 * BN + cl]
                             + se1.z * gWs[6 * BN + cl] + se1.w * gWs[7 * BN + cl];
                    float g1 = se0.x * gWs[0 * BN + cl + 1] + se0.y * gWs[1 * BN + cl + 1]
                             + se0.z * gWs[2 * BN + cl + 1] + se0.w * gWs[3 * BN + cl + 1]
                             + se1.x * gWs[4 * BN + cl + 1] + se1.y * gWs[5 * BN + cl + 1]
                             + se1.z * gWs[6 * BN + cl + 1] + se1.w * gWs[7 * BN + cl + 1];
                    v0 *= g0; v1 *= g1;
                }
                const size_t off = (size_t)row * H_DIM + col;
                uint2 o;
                o.x = tf32r(v0);
                o.y = tf32r(v1);
                *reinterpret_cast<uint2*>(C + off) = o;
            }
        }
    }
}

static constexpr int mma_smem(int BN, int gate) {
    return (3 * (128 * 36 + 32 * (BN + 8)) + (gate ? 8 * BN : 0)) * 4;
}

// ============ merged setup: round_w + s8e + s8t + zero(agg) ============
struct WSet { const float* src[11]; float* dst[11]; int n4[11]; };
static constexpr int SB_RW  = 176;
static constexpr int SB_S8E = SB_RW + 512;
static constexpr int SB_S8T = SB_S8E + 4096;
static constexpr int SB_ZERO = SB_S8T + 1024;
__global__ void setup_kernel(WSet ws,
                             const float* __restrict__ rbf, const float* __restrict__ Wr1,
                             float* __restrict__ s8e,
                             const float* __restrict__ sbf, const float* __restrict__ Ws1,
                             float* __restrict__ s8t,
                             float4* __restrict__ agg4)
{
    __shared__ float w[NSR * BAS];
    const int b = blockIdx.x, tid = threadIdx.x;

    if (b < SB_RW) {
        int seg = b >> 4, blk = b & 15;
        const float4* s = reinterpret_cast<const float4*>(ws.src[seg]);
        float4* d = reinterpret_cast<float4*>(ws.dst[seg]);
        int n4 = ws.n4[seg];
        for (int i = blk * 256 + tid; i < n4; i += 16 * 256) {
            float4 v = s[i];
            uint4 o;
            o.x = tf32r(v.x); o.y = tf32r(v.y); o.z = tf32r(v.z); o.w = tf32r(v.w);
            *reinterpret_cast<uint4*>(&d[i]) = o;
        }
    } else if (b < SB_S8E) {
        if (tid < NR * BAS) w[tid] = Wr1[tid];
        __syncthreads();
        int e = (b - SB_RW) * 256 + tid;
        float r[NR];
#pragma unroll
        for (int i = 0; i < NR; i++) r[i] = __ldg(rbf + (size_t)e * NR + i);
        float o[BAS];
#pragma unroll
        for (int j = 0; j < BAS; j++) {
            float s = 0.f;
#pragma unroll
            for (int i = 0; i < NR; i++) s += r[i] * w[i * BAS + j];
            o[j] = s;
        }
        reinterpret_cast<float4*>(s8e)[e * 2 + 0] = make_float4(o[0], o[1], o[2], o[3]);
        reinterpret_cast<float4*>(s8e)[e * 2 + 1] = make_float4(o[4], o[5], o[6], o[7]);
    } else if (b < SB_S8T) {
        for (int i = tid; i < NSR * BAS; i += 256) w[i] = Ws1[i];
        __syncthreads();
        int t = (b - SB_S8E) * 256 + tid;
        const float* srow = sbf + (size_t)t * NSR;
        float o[BAS];
#pragma unroll
        for (int j = 0; j < BAS; j++) o[j] = 0.0f;
#pragma unroll
        for (int i = 0; i < NSR; i++) {
            float r = __ldg(srow + i);
#pragma unroll
            for (int j = 0; j < BAS; j++) o[j] += r * w[i * BAS + j];
        }
        reinterpret_cast<float4*>(s8t)[(size_t)t * 2 + 0] = make_float4(o[0], o[1], o[2], o[3]);
        reinterpret_cast<float4*>(s8t)[(size_t)t * 2 + 1] = make_float4(o[4], o[5], o[6], o[7]);
    } else {
        const int n4 = E_EDGES * I_DIM / 4;
        for (int i = (b - SB_S8T) * 256 + tid; i < n4; i += 1024 * 256)
            agg4[i] = make_float4(0, 0, 0, 0);
    }
}

// ---------------- triplet pass (2x ILP) + PDL ----------------
__global__ void triplet_kernel(const float* __restrict__ s8t,
                               const int* __restrict__ idx_kj,
                               const int* __restrict__ idx_ji,
                               const float* __restrict__ W2,
                               const float* __restrict__ xkjd,
                               float* __restrict__ agg)
{
    __shared__ __align__(16) float sW2[BAS * I_DIM];
    for (int i = threadIdx.x; i < BAS * I_DIM; i += blockDim.x) sW2[i] = W2[i];
    __syncthreads();

    pdl_sync();      // xkjd producer (down-GEMM) complete
    pdl_trigger();

    const int lane  = threadIdx.x & 31;
    const int wglob = (blockIdx.x * blockDim.x + threadIdx.x) >> 5;
    const int nwarp = (gridDim.x * blockDim.x) >> 5;
    const int sub = lane >> 4;
    const int sl  = lane & 15;
    const int c   = sl * 4;

    float4 wf[BAS];
#pragma unroll
    for (int jj = 0; jj < BAS; jj++)
        wf[jj] = *reinterpret_cast<const float4*>(&sW2[jj * I_DIM + c]);

    for (int p = wglob; (p + nwarp) * 2 <= T_TRIP; p += 2 * nwarp) {
        const int t0 = p * 2 + sub;
        const int t1 = (p + nwarp) * 2 + sub;
        const float4* s8p0 = reinterpret_cast<const float4*>(s8t + (size_t)t0 * BAS);
        const float4* s8p1 = reinterpret_cast<const float4*>(s8t + (size_t)t1 * BAS);
        float4 a0 = __ldg(s8p0), a1 = __ldg(s8p0 + 1);
        float4 b0 = __ldg(s8p1), b1 = __ldg(s8p1 + 1);
        int ekj0 = __ldg(idx_kj + t0), eji0 = __ldg(idx_ji + t0);
        int ekj1 = __ldg(idx_kj + t1), eji1 = __ldg(idx_ji + t1);
        float4 xv0 = __ldg(reinterpret_cast<const float4*>(&xkjd[(size_t)ekj0 * I_DIM + c]));
        float4 xv1 = __ldg(reinterpret_cast<const float4*>(&xkjd[(size_t)ekj1 * I_DIM + c]));

        float4 m0 = make_float4(0, 0, 0, 0), m1 = make_float4(0, 0, 0, 0);
        float s0[BAS] = {a0.x, a0.y, a0.z, a0.w, a1.x, a1.y, a1.z, a1.w};
        float s1[BAS] = {b0.x, b0.y, b0.z, b0.w, b1.x, b1.y, b1.z, b1.w};
#pragma unroll
        for (int jj = 0; jj < BAS; jj++) {
            m0.x += s0[jj] * wf[jj].x; m0.y += s0[jj] * wf[jj].y;
            m0.z += s0[jj] * wf[jj].z; m0.w += s0[jj] * wf[jj].w;
            m1.x += s1[jj] * wf[jj].x; m1.y += s1[jj] * wf[jj].y;
            m1.z += s1[jj] * wf[jj].z; m1.w += s1[jj] * wf[jj].w;
        }
        m0.x *= xv0.x; m0.y *= xv0.y; m0.z *= xv0.z; m0.w *= xv0.w;
        m1.x *= xv1.x; m1.y *= xv1.y; m1.z *= xv1.z; m1.w *= xv1.w;
        atomicAdd(reinterpret_cast<float4*>(&agg[(size_t)eji0 * I_DIM + c]), m0);
        atomicAdd(reinterpret_cast<float4*>(&agg[(size_t)eji1 * I_DIM + c]), m1);
    }
}

// ---------------- PDL launch helper ----------------
template <typename F, typename... Args>
static void launch_pdl(F f, dim3 grid, dim3 block, int smem, Args... args)
{
    cudaLaunchConfig_t cfg = {};
    cfg.gridDim = grid;
    cfg.blockDim = block;
    cfg.dynamicSmemBytes = (size_t)smem;
    cfg.stream = 0;
    cudaLaunchAttribute at[1];
    at[0].id = cudaLaunchAttributeProgrammaticStreamSerialization;
    at[0].val.programmaticStreamSerializationAllowed = 1;
    cfg.attrs = at;
    cfg.numAttrs = 1;
    cudaLaunchKernelEx(&cfg, f, args...);
}

// ---------------- launch ----------------
extern "C" void kernel_launch(void* const* d_in, const int* in_sizes, int n_in,
                              void* d_out, int out_size)
{
    const float* x      = (const float*)d_in[0];
    const float* rbf    = (const float*)d_in[1];
    const float* sbf    = (const float*)d_in[2];
    const int*   idx_kj = (const int*)d_in[3];
    const int*   idx_ji = (const int*)d_in[4];
    const float* W_ji   = (const float*)d_in[5];
    const float* b_ji   = (const float*)d_in[6];
    const float* W_kj   = (const float*)d_in[7];
    const float* b_kj   = (const float*)d_in[8];
    const float* W_rbf1 = (const float*)d_in[9];
    const float* W_rbf2 = (const float*)d_in[10];
    const float* W_sbf1 = (const float*)d_in[11];
    const float* W_sbf2 = (const float*)d_in[12];
    const float* W_down = (const float*)d_in[13];
    const float* W_up   = (const float*)d_in[14];
    const float* Wb1_1  = (const float*)d_in[15];
    const float* bb1_1  = (const float*)d_in[16];
    const float* Wb1_2  = (const float*)d_in[17];
    const float* bb1_2  = (const float*)d_in[18];
    const float* W_lin  = (const float*)d_in[19];
    const float* b_lin  = (const float*)d_in[20];
    const float* Wa1_1  = (const float*)d_in[21];
    const float* ba1_1  = (const float*)d_in[22];
    const float* Wa1_2  = (const float*)d_in[23];
    const float* ba1_2  = (const float*)d_in[24];
    const float* Wa2_1  = (const float*)d_in[25];
    const float* ba2_1  = (const float*)d_in[26];
    const float* Wa2_2  = (const float*)d_in[27];
    const float* ba2_2  = (const float*)d_in[28];
    float* out = (float*)d_out;

    float *xji, *bufA, *bufB, *xkjd, *agg, *s8t, *s8e, *wr;
    cudaGetSymbolAddress((void**)&xji,  g_xji);
    cudaGetSymbolAddress((void**)&bufA, g_bufA);
    cudaGetSymbolAddress((void**)&bufB, g_bufB);
    cudaGetSymbolAddress((void**)&xkjd, g_xkjd);
    cudaGetSymbolAddress((void**)&agg,  g_agg);
    cudaGetSymbolAddress((void**)&s8t,  g_s8t);
    cudaGetSymbolAddress((void**)&s8e,  g_s8e);
    cudaGetSymbolAddress((void**)&wr,   g_wr);

    constexpr int SM_BIG   = mma_smem(128, 0);
    constexpr int SM_GATE  = mma_smem(128, 1);
    constexpr int SM_DOWN  = mma_smem(64, 0);
    cudaFuncSetAttribute(mma_gemm<128, 256, 0>, cudaFuncAttributeMaxDynamicSharedMemorySize, SM_BIG);
    cudaFuncSetAttribute(mma_gemm<64, 256, 0>,  cudaFuncAttributeMaxDynamicSharedMemorySize, SM_DOWN);
    cudaFuncSetAttribute(mma_gemm<128, 64, 0>,  cudaFuncAttributeMaxDynamicSharedMemorySize, SM_BIG);
    cudaFuncSetAttribute(dual_gemm,             cudaFuncAttributeMaxDynamicSharedMemorySize, SM_GATE);

    const dim3 gBig(2, E_EDGES / 128);
    const dim3 gDown(1, E_EDGES / 128);
    const dim3 gDual(4, E_EDGES / 128);
    const dim3 blk(256);

    WSet ws;
    const float* srcs[11] = {W_ji, W_kj, Wb1_1, Wb1_2, W_lin, Wa1_1, Wa1_2, Wa2_1, Wa2_2, W_down, W_up};
    const int offs[11]    = {WO_JI, WO_KJ, WO_B11, WO_B12, WO_LIN, WO_A11, WO_A12, WO_A21, WO_A22, WO_DOWN, WO_UP};
    const int n4s[11]     = {16384, 16384, 16384, 16384, 16384, 16384, 16384, 16384, 16384, 4096, 4096};
    for (int i = 0; i < 11; i++) { ws.src[i] = srcs[i]; ws.dst[i] = wr + offs[i]; ws.n4[i] = n4s[i]; }

    // 0: setup (weights round + s8e + s8t + zero agg)
    setup_kernel<<<SB_ZERO, 256>>>(ws, rbf, W_rbf1, s8e, sbf, W_sbf1, s8t, (float4*)agg);
    // 1: dual: x_kj_gated -> bufA, x_ji -> xji
    launch_pdl(dual_gemm, gDual, blk, SM_GATE, x, wr + WO_KJ, b_kj, wr + WO_JI, b_ji,
               bufA, xji, s8e, W_rbf2);
    // 2: x_kj_down = silu(x_kj_gated @ W_down)
    launch_pdl(mma_gemm<64, 256, 0>, gDown, blk, SM_DOWN,
               (const float*)bufA, wr + WO_DOWN, (const float*)nullptr, (const float*)nullptr,
               xkjd, I_DIM, (const float*)nullptr, (const float*)nullptr);
    // 3: triplet message passing
    launch_pdl(triplet_kernel, dim3(2048), blk, 0, (const float*)s8t, idx_kj, idx_ji,
               W_sbf2, (const float*)xkjd, agg);
    // 4: h = x_ji + silu(agg @ W_up)
    launch_pdl(mma_gemm<128, 64, 0>, gBig, blk, SM_BIG,
               (const float*)agg, wr + WO_UP, (const float*)nullptr, (const float*)xji,
               bufA, H_DIM, (const float*)nullptr, (const float*)nullptr);
    // 5-6: pre-skip residual pair
    launch_pdl(mma_gemm<128, 256, 0>, gBig, blk, SM_BIG,
               (const float*)bufA, wr + WO_B11, bb1_1, (const float*)nullptr,
               bufB, H_DIM, (const float*)nullptr, (const float*)nullptr);
    launch_pdl(mma_gemm<128, 256, 0>, gBig, blk, SM_BIG,
               (const float*)bufB, wr + WO_B12, bb1_2, (const float*)bufA,
               bufA, H_DIM, (const float*)nullptr, (const float*)nullptr);
    // 7: skip
    launch_pdl(mma_gemm<128, 256, 0>, gBig, blk, SM_BIG,
               (const float*)bufA, wr + WO_LIN, b_lin, x,
               bufB, H_DIM, (const float*)nullptr, (const float*)nullptr);
    // 8-9: post-skip residual pair 1
    launch_pdl(mma_gemm<128, 256, 0>, gBig, blk, SM_BIG,
               (const float*)bufB, wr + WO_A11, ba1_1, (const float*)nullptr,
               bufA, H_DIM, (const float*)nullptr, (const float*)nullptr);
    launch_pdl(mma_gemm<128, 256, 0>, gBig, blk, SM_BIG,
               (const float*)bufA, wr + WO_A12, ba1_2, (const float*)bufB,
               bufB, H_DIM, (const float*)nullptr, (const float*)nullptr);
    // 10-11: post-skip residual pair 2 -> final output
    launch_pdl(mma_gemm<128, 256, 0>, gBig, blk, SM_BIG,
               (const float*)bufB, wr + WO_A21, ba2_1, (const float*)nullptr,
               bufA, H_DIM, (const float*)nullptr, (const float*)nullptr);
    launch_pdl(mma_gemm<128, 256, 0>, gBig, blk, SM_BIG,
               (const float*)bufA, wr + WO_A22, ba2_2, (const float*)bufB,
               out, H_DIM, (const float*)nullptr, (const float*)nullptr);
}

// round 16
// speedup vs baseline: 1.4750x; 1.0239x over previous
#include <cuda_runtime.h>
#include <cstdint>
#include <cstddef>

// ---------------- problem constants ----------------
static constexpr int E_EDGES = 131072;
static constexpr int T_TRIP  = 1048576;
static constexpr int H_DIM   = 256;
static constexpr int I_DIM   = 64;
static constexpr int NR      = 6;
static constexpr int NSR     = 42;
static constexpr int BAS     = 8;

// ---------------- scratch (static device memory) ----------------
__device__ float g_xji [(size_t)E_EDGES * H_DIM];
__device__ float g_bufA[(size_t)E_EDGES * H_DIM];
__device__ float g_bufB[(size_t)E_EDGES * H_DIM];
__device__ float g_xkjd[(size_t)E_EDGES * I_DIM];
__device__ float g_agg [(size_t)E_EDGES * I_DIM];
__device__ float g_s8t [(size_t)T_TRIP * BAS];
__device__ float g_s8e [(size_t)E_EDGES * BAS];
__device__ float g_wr  [622592];

static constexpr int WO_JI   = 0;
static constexpr int WO_KJ   = 65536;
static constexpr int WO_B11  = 131072;
static constexpr int WO_B12  = 196608;
static constexpr int WO_LIN  = 262144;
static constexpr int WO_A11  = 327680;
static constexpr int WO_A12  = 393216;
static constexpr int WO_A21  = 458752;
static constexpr int WO_A22  = 524288;
static constexpr int WO_DOWN = 589824;
static constexpr int WO_UP   = 606208;

// ---------------- helpers ----------------
__device__ __forceinline__ uint32_t smem_to_u32(const void* p) {
    uint32_t a;
    asm("{ .reg .u64 t; cvta.to.shared.u64 t, %1; cvt.u32.u64 %0, t; }" : "=r"(a) : "l"(p));
    return a;
}
__device__ __forceinline__ uint32_t tf32r(float v) {
    uint32_t o; asm("cvt.rna.tf32.f32 %0, %1;" : "=r"(o) : "f"(v)); return o;
}
__device__ __forceinline__ float silu_f(float v) {
    return v * (1.0f / (1.0f + __expf(-v)));
}
__device__ __forceinline__ void cp_async16(uint32_t dst, const void* src) {
    asm volatile("cp.async.cg.shared.global [%0], [%1], 16;" :: "r"(dst), "l"(src));
}
__device__ __forceinline__ void mma_tf32(float d[4], const uint32_t a[4], const uint32_t b[2]) {
    asm volatile(
        "mma.sync.aligned.m16n8k8.row.col.f32.tf32.tf32.f32 "
        "{%0,%1,%2,%3}, {%4,%5,%6,%7}, {%8,%9}, {%0,%1,%2,%3};"
        : "+f"(d[0]), "+f"(d[1]), "+f"(d[2]), "+f"(d[3])
        : "r"(a[0]), "r"(a[1]), "r"(a[2]), "r"(a[3]), "r"(b[0]), "r"(b[1]));
}
__device__ __forceinline__ void pdl_sync() {
#if __CUDA_ARCH__ >= 900
    cudaGridDependencySynchronize();
#endif
}
__device__ __forceinline__ void pdl_trigger() {
#if __CUDA_ARCH__ >= 900
    cudaTriggerProgrammaticLaunchCompletion();
#endif
}

// ============ occ-3 tf32 GEMM: BN=64, BK=16, DEPTH=4, 8 warps (4M x 2N) ============
// warp tile 32 x 32; acc 2x4x4 = 32 regs -> ~80 regs total -> 3 CTAs/SM (24 warps).
// A stride 20 (frag bank 20g+q distinct), B stride 72 (frag bank 8q+g distinct).
template <int K>
__global__ void __launch_bounds__(256, 3)
gemm3(const float* __restrict__ A, const float* __restrict__ W,
      const float* __restrict__ bias, const float* __restrict__ res,
      float* __restrict__ C, int Nfull)
{
    constexpr int BM = 128, BN = 64, BK = 16, DEPTH = 4;
    constexpr int KT = K / BK;
    constexpr int AS = BK + 4;                 // 20
    constexpr int A_STAGE = BM * AS;           // 2560
    constexpr int BS = BN + 8;                 // 72
    constexpr int B_STAGE = BK * BS;           // 1152
    constexpr int NF = 4;                      // 32 cols / 8

    extern __shared__ float smf[];
    float* As = smf;
    float* Bs = smf + DEPTH * A_STAGE;
    const uint32_t uA = smem_to_u32(As);
    const uint32_t uB = smem_to_u32(Bs);

    const int tid = threadIdx.x, lane = tid & 31, wid = tid >> 5;
    const int warpM = wid >> 1, warpN = wid & 1;
    const int row0 = blockIdx.y * BM;
    const int col0 = blockIdx.x * BN;
    const int g = lane >> 2, q = lane & 3;

    auto loadW = [&](int s, int kt) {
        // B: 16 x 64 = 256 float4 chunks, 1 per thread
        int k = tid >> 4, n4 = (tid & 15) * 4;
        cp_async16(uB + (uint32_t)(s * B_STAGE + k * BS + n4) * 4,
                   W + (size_t)(kt * BK + k) * Nfull + col0 + n4);
    };
    auto loadA = [&](int s, int kt) {
        // A: 128 x 16 = 512 float4 chunks, 2 per thread
#pragma unroll
        for (int i = 0; i < 2; i++) {
            int id = tid + i * 256;
            int m = id >> 2, c4 = (id & 3) * 4;
            cp_async16(uA + (uint32_t)(s * A_STAGE + m * AS + c4) * 4,
                       A + (size_t)(row0 + m) * K + kt * BK + c4);
        }
    };

    // stable W stages before PDL sync
#pragma unroll
    for (int s = 0; s < DEPTH - 1; s++)
        if (s < KT) loadW(s, s);

    pdl_sync();
    pdl_trigger();

    float acc[2][NF][4];
#pragma unroll
    for (int mf = 0; mf < 2; mf++)
#pragma unroll
        for (int nf = 0; nf < NF; nf++)
#pragma unroll
            for (int v = 0; v < 4; v++) acc[mf][nf][v] = 0.0f;

#pragma unroll
    for (int s = 0; s < DEPTH - 1; s++) {
        if (s < KT) loadA(s, s);
        asm volatile("cp.async.commit_group;" ::: "memory");
    }

    for (int it = 0; it < KT; it++) {
        asm volatile("cp.async.wait_group %0;" :: "n"(DEPTH - 2) : "memory");
        __syncthreads();
        const int nx = it + DEPTH - 1;
        if (nx < KT) { loadA(nx % DEPTH, nx); loadW(nx % DEPTH, nx); }
        asm volatile("cp.async.commit_group;" ::: "memory");

        const int s = it % DEPTH;
        const float* Asb = As + s * A_STAGE;
        const float* Bsb = Bs + s * B_STAGE;
#pragma unroll
        for (int ks = 0; ks < 2; ks++) {
            uint32_t af[2][4];
            uint32_t bf[NF][2];
#pragma unroll
            for (int mf = 0; mf < 2; mf++) {
                int r = warpM * 32 + mf * 16 + g;
                af[mf][0] = __float_as_uint(Asb[r * AS + ks * 8 + q]);
                af[mf][1] = __float_as_uint(Asb[(r + 8) * AS + ks * 8 + q]);
                af[mf][2] = __float_as_uint(Asb[r * AS + ks * 8 + q + 4]);
                af[mf][3] = __float_as_uint(Asb[(r + 8) * AS + ks * 8 + q + 4]);
            }
#pragma unroll
            for (int nf = 0; nf < NF; nf++) {
                int c = warpN * 32 + nf * 8 + g;
                bf[nf][0] = __float_as_uint(Bsb[(ks * 8 + q) * BS + c]);
                bf[nf][1] = __float_as_uint(Bsb[(ks * 8 + q + 4) * BS + c]);
            }
#pragma unroll
            for (int mf = 0; mf < 2; mf++)
#pragma unroll
                for (int nf = 0; nf < NF; nf++)
                    mma_tf32(acc[mf][nf], af[mf], bf[nf]);
        }
    }

#pragma unroll
    for (int mf = 0; mf < 2; mf++) {
#pragma unroll
        for (int nf = 0; nf < NF; nf++) {
            const int col = col0 + warpN * 32 + nf * 8 + 2 * q;
            float bv0 = 0.0f, bv1 = 0.0f;
            if (bias) { bv0 = bias[col]; bv1 = bias[col + 1]; }
#pragma unroll
            for (int h = 0; h < 2; h++) {
                const int row = row0 + warpM * 32 + mf * 16 + g + h * 8;
                float v0 = silu_f(acc[mf][nf][h * 2 + 0] + bv0);
                float v1 = silu_f(acc[mf][nf][h * 2 + 1] + bv1);
                const size_t off = (size_t)row * Nfull + col;
                if (res) {
                    float2 r = *reinterpret_cast<const float2*>(res + off);
                    v0 += r.x; v1 += r.y;
                }
                uint2 o;
                o.x = tf32r(v0);
                o.y = tf32r(v1);
                *reinterpret_cast<uint2*>(C + off) = o;
            }
        }
    }
}
static constexpr int SM_G3 = 4 * (128 * 20 + 16 * 72) * 4;   // 59,392 B

// ============ dual GEMM (R13, occ 2, gate fused): kj + ji, shared A = x ============
static constexpr int BM_ = 128, BK_ = 32, DEPTH_ = 3;
static constexpr int AS_STRIDE_ = BK_ + 4;
static constexpr int AS_STAGE_  = BM_ * AS_STRIDE_;

__global__ void __launch_bounds__(256, 2)
dual_gemm(const float* __restrict__ A,
          const float* __restrict__ Wkj, const float* __restrict__ bkj,
          const float* __restrict__ Wji, const float* __restrict__ bji,
          float* __restrict__ Ckj, float* __restrict__ Cji,
          const float* __restrict__ s8e, const float* __restrict__ Wg)
{
    constexpr int BN = 128, K = 256, KT = K / BK_;
    constexpr int BS_STRIDE = BN + 8;
    constexpr int BS_STAGE  = BK_ * BS_STRIDE;
    constexpr int NF = BN / 16;

    extern __shared__ float smf[];
    float* As = smf;
    float* Bs = smf + DEPTH_ * AS_STAGE_;
    float* gWs = Bs + DEPTH_ * BS_STAGE;
    const uint32_t smemA = smem_to_u32(As);
    const uint32_t smemB = smem_to_u32(Bs);

    const int tid = threadIdx.x, lane = tid & 31, wid = tid >> 5;
    const int warpM = wid >> 1, warpN = wid & 1;
    const int row0 = blockIdx.y * BM_;
    const int is_ji = blockIdx.x >> 1;
    const int col0 = (blockIdx.x & 1) * BN;
    const int g = lane >> 2, q = lane & 3;

    const float* W    = is_ji ? Wji : Wkj;
    const float* bias = is_ji ? bji : bkj;
    float* C          = is_ji ? Cji : Ckj;

    auto loadW = [&](int s, int kt) {
        const int k0 = kt * BK_;
        constexpr int BCH = BK_ * BN / 4;
#pragma unroll
        for (int i = 0; i < BCH / 256; i++) {
            int id = tid + i * 256;
            int k = id / (BN / 4), n4 = (id % (BN / 4)) * 4;
            cp_async16(smemB + (uint32_t)(s * BS_STAGE + k * BS_STRIDE + n4) * 4,
                       W + (size_t)(k0 + k) * H_DIM + col0 + n4);
        }
    };
    auto loadA = [&](int s, int kt) {
        const int k0 = kt * BK_;
#pragma unroll
        for (int i = 0; i < 4; i++) {
            int id = tid + i * 256;
            int m = id >> 3, c4 = (id & 7) * 4;
            cp_async16(smemA + (uint32_t)(s * AS_STAGE_ + m * AS_STRIDE_ + c4) * 4,
                       A + (size_t)(row0 + m) * K + k0 + c4);
        }
    };

    if (!is_ji) {
        for (int i = tid; i < BAS * BN; i += 256) {
            int j = i / BN, n = i % BN;
            gWs[j * BN + n] = Wg[j * H_DIM + col0 + n];
        }
    }
#pragma unroll
    for (int s = 0; s < DEPTH_ - 1; s++) loadW(s, s);

    pdl_sync();
    pdl_trigger();

    float acc[2][NF][4];
#pragma unroll
    for (int mf = 0; mf < 2; mf++)
#pragma unroll
        for (int nf = 0; nf < NF; nf++)
#pragma unroll
            for (int v = 0; v < 4; v++) acc[mf][nf][v] = 0.0f;

#pragma unroll
    for (int s = 0; s < DEPTH_ - 1; s++) {
        loadA(s, s);
        asm volatile("cp.async.commit_group;" ::: "memory");
    }

    for (int it = 0; it < KT; it++) {
        asm volatile("cp.async.wait_group %0;" :: "n"(DEPTH_ - 2) : "memory");
        __syncthreads();
        const int nx = it + DEPTH_ - 1;
        if (nx < KT) { loadA(nx % DEPTH_, nx); loadW(nx % DEPTH_, nx); }
        asm volatile("cp.async.commit_group;" ::: "memory");

        const int s = it % DEPTH_;
        const float* Asb = As + s * AS_STAGE_;
        const float* Bsb = Bs + s * BS_STAGE;
#pragma unroll
        for (int ks = 0; ks < 4; ks++) {
            uint32_t af[2][4];
            uint32_t bf[NF][2];
#pragma unroll
            for (int mf = 0; mf < 2; mf++) {
                int r = warpM * 32 + mf * 16 + g;
                af[mf][0] = __float_as_uint(Asb[r * AS_STRIDE_ + ks * 8 + q]);
                af[mf][1] = __float_as_uint(Asb[(r + 8) * AS_STRIDE_ + ks * 8 + q]);
                af[mf][2] = __float_as_uint(Asb[r * AS_STRIDE_ + ks * 8 + q + 4]);
                af[mf][3] = __float_as_uint(Asb[(r + 8) * AS_STRIDE_ + ks * 8 + q + 4]);
            }
#pragma unroll
            for (int nf = 0; nf < NF; nf++) {
                int c = warpN * (BN / 2) + nf * 8 + g;
                bf[nf][0] = __float_as_uint(Bsb[(ks * 8 + q) * BS_STRIDE + c]);
                bf[nf][1] = __float_as_uint(Bsb[(ks * 8 + q + 4) * BS_STRIDE + c]);
            }
#pragma unroll
            for (int mf = 0; mf < 2; mf++)
#pragma unroll
                for (int nf = 0; nf < NF; nf++)
                    mma_tf32(acc[mf][nf], af[mf], bf[nf]);
        }
    }

#pragma unroll
    for (int mf = 0; mf < 2; mf++) {
#pragma unroll
        for (int h = 0; h < 2; h++) {
            const int row = row0 + warpM * 32 + mf * 16 + g + h * 8;
            float4 se0 = make_float4(0, 0, 0, 0), se1 = make_float4(0, 0, 0, 0);
            if (!is_ji) {
                const float4* sp = reinterpret_cast<const float4*>(s8e + (size_t)row * BAS);
                se0 = __ldg(sp); se1 = __ldg(sp + 1);
            }
#pragma unroll
            for (int nf = 0; nf < NF; nf++) {
                const int cl = warpN * (BN / 2) + nf * 8 + 2 * q;
                const int col = col0 + cl;
                float v0 = silu_f(acc[mf][nf][h * 2 + 0] + bias[col]);
                float v1 = silu_f(acc[mf][nf][h * 2 + 1] + bias[col + 1]);
                if (!is_ji) {
                    float g0 = se0.x * gWs[0 * BN + cl] + se0.y * gWs[1 * BN + cl]
                             + se0.z * gWs[2 * BN + cl] + se0.w * gWs[3 * BN + cl]
                             + se1.x * gWs[4 * BN + cl] + se1.y * gWs[5 * BN + cl]
                             + se1.z * gWs[6 * BN + cl] + se1.w * gWs[7 * BN + cl];
                    float g1 = se0.x * gWs[0 * BN + cl + 1] + se0.y * gWs[1 * BN + cl + 1]
                             + se0.z * gWs[2 * BN + cl + 1] + se0.w * gWs[3 * BN + cl + 1]
                             + se1.x * gWs[4 * BN + cl + 1] + se1.y * gWs[5 * BN + cl + 1]
                             + se1.z * gWs[6 * BN + cl + 1] + se1.w * gWs[7 * BN + cl + 1];
                    v0 *= g0; v1 *= g1;
                }
                const size_t off = (size_t)row * H_DIM + col;
                uint2 o;
                o.x = tf32r(v0);
                o.y = tf32r(v1);
                *reinterpret_cast<uint2*>(C + off) = o;
            }
        }
    }
}
static constexpr int SM_GATE = (3 * (128 * 36 + 32 * 136) + 8 * 128) * 4;

// ============ merged setup ============
struct WSet { const float* src[11]; float* dst[11]; int n4[11]; };
static constexpr int SB_RW  = 176;
static constexpr int SB_S8E = SB_RW + 512;
static constexpr int SB_S8T = SB_S8E + 4096;
static constexpr int SB_ZERO = SB_S8T + 1024;
__global__ void setup_kernel(WSet ws,
                             const float* __restrict__ rbf, const float* __restrict__ Wr1,
                             float* __restrict__ s8e,
                             const float* __restrict__ sbf, const float* __restrict__ Ws1,
                             float* __restrict__ s8t,
                             float4* __restrict__ agg4)
{
    __shared__ float w[NSR * BAS];
    const int b = blockIdx.x, tid = threadIdx.x;

    if (b < SB_RW) {
        int seg = b >> 4, blk = b & 15;
        const float4* s = reinterpret_cast<const float4*>(ws.src[seg]);
        float4* d = reinterpret_cast<float4*>(ws.dst[seg]);
        int n4 = ws.n4[seg];
        for (int i = blk * 256 + tid; i < n4; i += 16 * 256) {
            float4 v = s[i];
            uint4 o;
            o.x = tf32r(v.x); o.y = tf32r(v.y); o.z = tf32r(v.z); o.w = tf32r(v.w);
            *reinterpret_cast<uint4*>(&d[i]) = o;
        }
    } else if (b < SB_S8E) {
        if (tid < NR * BAS) w[tid] = Wr1[tid];
        __syncthreads();
        int e = (b - SB_RW) * 256 + tid;
        float r[NR];
#pragma unroll
        for (int i = 0; i < NR; i++) r[i] = __ldg(rbf + (size_t)e * NR + i);
        float o[BAS];
#pragma unroll
        for (int j = 0; j < BAS; j++) {
            float s = 0.f;
#pragma unroll
            for (int i = 0; i < NR; i++) s += r[i] * w[i * BAS + j];
            o[j] = s;
        }
        reinterpret_cast<float4*>(s8e)[e * 2 + 0] = make_float4(o[0], o[1], o[2], o[3]);
        reinterpret_cast<float4*>(s8e)[e * 2 + 1] = make_float4(o[4], o[5], o[6], o[7]);
    } else if (b < SB_S8T) {
        for (int i = tid; i < NSR * BAS; i += 256) w[i] = Ws1[i];
        __syncthreads();
        int t = (b - SB_S8E) * 256 + tid;
        const float* srow = sbf + (size_t)t * NSR;
        float o[BAS];
#pragma unroll
        for (int j = 0; j < BAS; j++) o[j] = 0.0f;
#pragma unroll
        for (int i = 0; i < NSR; i++) {
            float r = __ldg(srow + i);
#pragma unroll
            for (int j = 0; j < BAS; j++) o[j] += r * w[i * BAS + j];
        }
        reinterpret_cast<float4*>(s8t)[(size_t)t * 2 + 0] = make_float4(o[0], o[1], o[2], o[3]);
        reinterpret_cast<float4*>(s8t)[(size_t)t * 2 + 1] = make_float4(o[4], o[5], o[6], o[7]);
    } else {
        const int n4 = E_EDGES * I_DIM / 4;
        for (int i = (b - SB_S8T) * 256 + tid; i < n4; i += 1024 * 256)
            agg4[i] = make_float4(0, 0, 0, 0);
    }
}

// ---------------- triplet pass (2x ILP) + PDL ----------------
__global__ void triplet_kernel(const float* __restrict__ s8t,
                               const int* __restrict__ idx_kj,
                               const int* __restrict__ idx_ji,
                               const float* __restrict__ W2,
                               const float* __restrict__ xkjd,
                               float* __restrict__ agg)
{
    __shared__ __align__(16) float sW2[BAS * I_DIM];
    for (int i = threadIdx.x; i < BAS * I_DIM; i += blockDim.x) sW2[i] = W2[i];
    __syncthreads();

    pdl_sync();
    pdl_trigger();

    const int lane  = threadIdx.x & 31;
    const int wglob = (blockIdx.x * blockDim.x + threadIdx.x) >> 5;
    const int nwarp = (gridDim.x * blockDim.x) >> 5;
    const int sub = lane >> 4;
    const int sl  = lane & 15;
    const int c   = sl * 4;

    float4 wf[BAS];
#pragma unroll
    for (int jj = 0; jj < BAS; jj++)
        wf[jj] = *reinterpret_cast<const float4*>(&sW2[jj * I_DIM + c]);

    for (int p = wglob; (p + nwarp) * 2 <= T_TRIP; p += 2 * nwarp) {
        const int t0 = p * 2 + sub;
        const int t1 = (p + nwarp) * 2 + sub;
        const float4* s8p0 = reinterpret_cast<const float4*>(s8t + (size_t)t0 * BAS);
        const float4* s8p1 = reinterpret_cast<const float4*>(s8t + (size_t)t1 * BAS);
        float4 a0 = __ldg(s8p0), a1 = __ldg(s8p0 + 1);
        float4 b0 = __ldg(s8p1), b1 = __ldg(s8p1 + 1);
        int ekj0 = __ldg(idx_kj + t0), eji0 = __ldg(idx_ji + t0);
        int ekj1 = __ldg(idx_kj + t1), eji1 = __ldg(idx_ji + t1);
        float4 xv0 = __ldg(reinterpret_cast<const float4*>(&xkjd[(size_t)ekj0 * I_DIM + c]));
        float4 xv1 = __ldg(reinterpret_cast<const float4*>(&xkjd[(size_t)ekj1 * I_DIM + c]));

        float4 m0 = make_float4(0, 0, 0, 0), m1 = make_float4(0, 0, 0, 0);
        float s0[BAS] = {a0.x, a0.y, a0.z, a0.w, a1.x, a1.y, a1.z, a1.w};
        float s1[BAS] = {b0.x, b0.y, b0.z, b0.w, b1.x, b1.y, b1.z, b1.w};
#pragma unroll
        for (int jj = 0; jj < BAS; jj++) {
            m0.x += s0[jj] * wf[jj].x; m0.y += s0[jj] * wf[jj].y;
            m0.z += s0[jj] * wf[jj].z; m0.w += s0[jj] * wf[jj].w;
            m1.x += s1[jj] * wf[jj].x; m1.y += s1[jj] * wf[jj].y;
            m1.z += s1[jj] * wf[jj].z; m1.w += s1[jj] * wf[jj].w;
        }
        m0.x *= xv0.x; m0.y *= xv0.y; m0.z *= xv0.z; m0.w *= xv0.w;
        m1.x *= xv1.x; m1.y *= xv1.y; m1.z *= xv1.z; m1.w *= xv1.w;
        atomicAdd(reinterpret_cast<float4*>(&agg[(size_t)eji0 * I_DIM + c]), m0);
        atomicAdd(reinterpret_cast<float4*>(&agg[(size_t)eji1 * I_DIM + c]), m1);
    }
}

// ---------------- PDL launch helper ----------------
template <typename F, typename... Args>
static void launch_pdl(F f, dim3 grid, dim3 block, int smem, Args... args)
{
    cudaLaunchConfig_t cfg = {};
    cfg.gridDim = grid;
    cfg.blockDim = block;
    cfg.dynamicSmemBytes = (size_t)smem;
    cfg.stream = 0;
    cudaLaunchAttribute at[1];
    at[0].id = cudaLaunchAttributeProgrammaticStreamSerialization;
    at[0].val.programmaticStreamSerializationAllowed = 1;
    cfg.attrs = at;
    cfg.numAttrs = 1;
    cudaLaunchKernelEx(&cfg, f, args...);
}

// ---------------- launch ----------------
extern "C" void kernel_launch(void* const* d_in, const int* in_sizes, int n_in,
                              void* d_out, int out_size)
{
    const float* x      = (const float*)d_in[0];
    const float* rbf    = (const float*)d_in[1];
    const float* sbf    = (const float*)d_in[2];
    const int*   idx_kj = (const int*)d_in[3];
    const int*   idx_ji = (const int*)d_in[4];
    const float* W_ji   = (const float*)d_in[5];
    const float* b_ji   = (const float*)d_in[6];
    const float* W_kj   = (const float*)d_in[7];
    const float* b_kj   = (const float*)d_in[8];
    const float* W_rbf1 = (const float*)d_in[9];
    const float* W_rbf2 = (const float*)d_in[10];
    const float* W_sbf1 = (const float*)d_in[11];
    const float* W_sbf2 = (const float*)d_in[12];
    const float* W_down = (const float*)d_in[13];
    const float* W_up   = (const float*)d_in[14];
    const float* Wb1_1  = (const float*)d_in[15];
    const float* bb1_1  = (const float*)d_in[16];
    const float* Wb1_2  = (const float*)d_in[17];
    const float* bb1_2  = (const float*)d_in[18];
    const float* W_lin  = (const float*)d_in[19];
    const float* b_lin  = (const float*)d_in[20];
    const float* Wa1_1  = (const float*)d_in[21];
    const float* ba1_1  = (const float*)d_in[22];
    const float* Wa1_2  = (const float*)d_in[23];
    const float* ba1_2  = (const float*)d_in[24];
    const float* Wa2_1  = (const float*)d_in[25];
    const float* ba2_1  = (const float*)d_in[26];
    const float* Wa2_2  = (const float*)d_in[27];
    const float* ba2_2  = (const float*)d_in[28];
    float* out = (float*)d_out;

    float *xji, *bufA, *bufB, *xkjd, *agg, *s8t, *s8e, *wr;
    cudaGetSymbolAddress((void**)&xji,  g_xji);
    cudaGetSymbolAddress((void**)&bufA, g_bufA);
    cudaGetSymbolAddress((void**)&bufB, g_bufB);
    cudaGetSymbolAddress((void**)&xkjd, g_xkjd);
    cudaGetSymbolAddress((void**)&agg,  g_agg);
    cudaGetSymbolAddress((void**)&s8t,  g_s8t);
    cudaGetSymbolAddress((void**)&s8e,  g_s8e);
    cudaGetSymbolAddress((void**)&wr,   g_wr);

    cudaFuncSetAttribute(gemm3<256>, cudaFuncAttributeMaxDynamicSharedMemorySize, SM_G3);
    cudaFuncSetAttribute(gemm3<64>,  cudaFuncAttributeMaxDynamicSharedMemorySize, SM_G3);
    cudaFuncSetAttribute(dual_gemm,  cudaFuncAttributeMaxDynamicSharedMemorySize, SM_GATE);

    const dim3 gB64(4, E_EDGES / 128);   // N=256 as 4 x BN=64
    const dim3 gD64(1, E_EDGES / 128);   // N=64
    const dim3 gDual(4, E_EDGES / 128);
    const dim3 blk(256);

    WSet ws;
    const float* srcs[11] = {W_ji, W_kj, Wb1_1, Wb1_2, W_lin, Wa1_1, Wa1_2, Wa2_1, Wa2_2, W_down, W_up};
    const int offs[11]    = {WO_JI, WO_KJ, WO_B11, WO_B12, WO_LIN, WO_A11, WO_A12, WO_A21, WO_A22, WO_DOWN, WO_UP};
    const int n4s[11]     = {16384, 16384, 16384, 16384, 16384, 16384, 16384, 16384, 16384, 4096, 4096};
    for (int i = 0; i < 11; i++) { ws.src[i] = srcs[i]; ws.dst[i] = wr + offs[i]; ws.n4[i] = n4s[i]; }

    // 0: setup
    setup_kernel<<<SB_ZERO, 256>>>(ws, rbf, W_rbf1, s8e, sbf, W_sbf1, s8t, (float4*)agg);
    // 1: dual: x_kj_gated -> bufA, x_ji -> xji
    launch_pdl(dual_gemm, gDual, blk, SM_GATE, x, wr + WO_KJ, b_kj, wr + WO_JI, b_ji,
               bufA, xji, s8e, W_rbf2);
    // 2: x_kj_down = silu(x_kj_gated @ W_down)
    launch_pdl(gemm3<256>, gD64, blk, SM_G3,
               (const float*)bufA, wr + WO_DOWN, (const float*)nullptr, (const float*)nullptr,
               xkjd, I_DIM);
    // 3: triplet message passing
    launch_pdl(triplet_kernel, dim3(2048), blk, 0, (const float*)s8t, idx_kj, idx_ji,
               W_sbf2, (const float*)xkjd, agg);
    // 4: h = x_ji + silu(agg @ W_up)
    launch_pdl(gemm3<64>, gB64, blk, SM_G3,
               (const float*)agg, wr + WO_UP, (const float*)nullptr, (const float*)xji,
               bufA, H_DIM);
    // 5-6: pre-skip residual pair
    launch_pdl(gemm3<256>, gB64, blk, SM_G3,
               (const float*)bufA, wr + WO_B11, bb1_1, (const float*)nullptr, bufB, H_DIM);
    launch_pdl(gemm3<256>, gB64, blk, SM_G3,
               (const float*)bufB, wr + WO_B12, bb1_2, (const float*)bufA, bufA, H_DIM);
    // 7: skip
    launch_pdl(gemm3<256>, gB64, blk, SM_G3,
               (const float*)bufA, wr + WO_LIN, b_lin, x, bufB, H_DIM);
    // 8-9: post-skip residual pair 1
    launch_pdl(gemm3<256>, gB64, blk, SM_G3,
               (const float*)bufB, wr + WO_A11, ba1_1, (const float*)nullptr, bufA, H_DIM);
    launch_pdl(gemm3<256>, gB64, blk, SM_G3,
               (const float*)bufA, wr + WO_A12, ba1_2, (const float*)bufB, bufB, H_DIM);
    // 10-11: post-skip residual pair 2 -> final output
    launch_pdl(gemm3<256>, gB64, blk, SM_G3,
               (const float*)bufB, wr + WO_A21, ba2_1, (const float*)nullptr, bufA, H_DIM);
    launch_pdl(gemm3<256>, gB64, blk, SM_G3,
               (const float*)bufA, wr + WO_A22, ba2_2, (const float*)bufB, out, H_DIM);
}